// round 2
// baseline (speedup 1.0000x reference)
#include <cuda_runtime.h>
#include <cstdint>
#include <cstddef>

// ---------------- problem constants ----------------
#define BB 2
#define CC 256
#define HH 128
#define WW 128
#define HW 16384           // H*W
#define MPIX 32768         // B*H*W
#define NCLS 80
#define NMS_CAND 1000
#define MAX_DET 100

// ---------------- scratch (device globals; no allocs allowed) ----------------
__device__ float g_X0[(size_t)MPIX * 256];     // pixel-major input
__device__ float g_bufA[(size_t)MPIX * 256];
__device__ float g_bufB[(size_t)MPIX * 256];
__device__ float g_cls[(size_t)MPIX * 81];
__device__ float g_obj[(size_t)MPIX * 2];
__device__ float g_box[(size_t)MPIX * 4];
__device__ float g_score[MPIX];
__device__ int   g_label[MPIX];
__device__ float g_boxes[(size_t)MPIX * 4];
__device__ float g_cand_sc[BB * NMS_CAND];
__device__ int   g_cand_lab[BB * NMS_CAND];
__device__ float g_cand_box[BB * NMS_CAND * 4];
__device__ unsigned g_mask[(size_t)BB * NMS_CAND * 32];
__device__ unsigned g_keep[BB * 32];

// ---------------- feat (B,C,H,W) -> X0 [B*HW][C] ----------------
__global__ void transpose_k(const float* __restrict__ feat) {
    __shared__ float t[32][33];
    int hw0 = blockIdx.x * 32;
    int c0  = blockIdx.y * 32;
    int b   = blockIdx.z;
    int tx = threadIdx.x, ty = threadIdx.y;   // block (32,8)
    #pragma unroll
    for (int i = 0; i < 32; i += 8)
        t[ty + i][tx] = feat[((size_t)(b * CC + c0 + ty + i)) * HW + hw0 + tx];
    __syncthreads();
    #pragma unroll
    for (int i = 0; i < 32; i += 8)
        g_X0[((size_t)(b * HW + hw0 + ty + i)) * 256 + c0 + tx] = t[tx][ty + i];
}

// ---------------- fp32 GEMM: C[m][n] = sum_k A[m][k]*W[n][k] + bias[n] (+A[m][n]) ----------------
__global__ void __launch_bounds__(256) gemm_k(
    const float* __restrict__ A,   // [M][256]
    const float* __restrict__ Wt,  // [N][256]
    const float* __restrict__ bias,
    float* __restrict__ Cout,      // [M][ldc]
    int N, int ldc, int residual)
{
    __shared__ float As[16][128];
    __shared__ float Bs[16][132];
    const int m0 = blockIdx.y * 128;
    const int n0 = blockIdx.x * 128;
    const int tid = threadIdx.x;
    const int tx = tid & 15, ty = tid >> 4;

    float acc[8][8];
    #pragma unroll
    for (int i = 0; i < 8; i++)
        #pragma unroll
        for (int j = 0; j < 8; j++) acc[i][j] = 0.f;

    for (int k0 = 0; k0 < 256; k0 += 16) {
        #pragma unroll
        for (int l = 0; l < 2; l++) {
            int idx = tid + l * 256;
            int row = idx >> 2;
            int kc  = (idx & 3) << 2;
            const float4 v = *(const float4*)(A + (size_t)(m0 + row) * 256 + k0 + kc);
            As[kc + 0][row] = v.x; As[kc + 1][row] = v.y;
            As[kc + 2][row] = v.z; As[kc + 3][row] = v.w;
        }
        #pragma unroll
        for (int l = 0; l < 2; l++) {
            int idx = tid + l * 256;
            int row = idx >> 2;
            int kc  = (idx & 3) << 2;
            float4 v = make_float4(0.f, 0.f, 0.f, 0.f);
            if (n0 + row < N)
                v = *(const float4*)(Wt + (size_t)(n0 + row) * 256 + k0 + kc);
            Bs[kc + 0][row] = v.x; Bs[kc + 1][row] = v.y;
            Bs[kc + 2][row] = v.z; Bs[kc + 3][row] = v.w;
        }
        __syncthreads();
        #pragma unroll
        for (int kk = 0; kk < 16; kk++) {
            float a[8], b[8];
            #pragma unroll
            for (int i = 0; i < 8; i++) a[i] = As[kk][ty * 8 + i];
            #pragma unroll
            for (int j = 0; j < 8; j++) b[j] = Bs[kk][tx * 8 + j];
            #pragma unroll
            for (int i = 0; i < 8; i++)
                #pragma unroll
                for (int j = 0; j < 8; j++)
                    acc[i][j] = fmaf(a[i], b[j], acc[i][j]);
        }
        __syncthreads();
    }
    #pragma unroll
    for (int i = 0; i < 8; i++) {
        int m = m0 + ty * 8 + i;
        #pragma unroll
        for (int j = 0; j < 8; j++) {
            int n = n0 + tx * 8 + j;
            if (n < N) {
                float v = acc[i][j] + bias[n];
                if (residual) v += A[(size_t)m * 256 + n];
                Cout[(size_t)m * ldc + n] = v;
            }
        }
    }
}

// ---------------- decode: scores / labels / boxes ----------------
__device__ __forceinline__ float sigmoidf_(float x) { return 1.f / (1.f + expf(-x)); }

__global__ void decode_k() {
    int n = blockIdx.x * blockDim.x + threadIdx.x;
    if (n >= MPIX) return;
    int hw = n & (HW - 1);
    int h = hw >> 7, w = hw & 127;

    float objp = sigmoidf_(g_obj[(size_t)n * 2]);
    float best = -1.f; int bl = 0;
    #pragma unroll 4
    for (int c = 0; c < NCLS; c++) {
        float p = sigmoidf_(g_cls[(size_t)n * 81 + c]) * objp;
        if (p > best) { best = p; bl = c; }
    }
    g_score[n] = best;
    g_label[n] = bl;

    float px = (w + 0.5f) * 8.f;
    float py = (h + 0.5f) * 8.f;
    float l = expf(g_box[(size_t)n * 4 + 0]) * 8.f;
    float t = expf(g_box[(size_t)n * 4 + 1]) * 8.f;
    float r = expf(g_box[(size_t)n * 4 + 2]) * 8.f;
    float d = expf(g_box[(size_t)n * 4 + 3]) * 8.f;
    g_boxes[(size_t)n * 4 + 0] = px - l;
    g_boxes[(size_t)n * 4 + 1] = py - t;
    g_boxes[(size_t)n * 4 + 2] = px + r;
    g_boxes[(size_t)n * 4 + 3] = py + d;
}

// ---------------- per-batch full bitonic sort of 16384 packed keys ----------------
// key = (~score_bits << 32) | index : ascending sort == (score desc, index asc),
// matching jax.lax.top_k tie-breaking exactly.
__global__ void sort_k() {
    extern __shared__ unsigned long long skey[];
    int b = blockIdx.x;
    int tid = threadIdx.x;
    for (int i = tid; i < HW; i += 1024) {
        float s = g_score[b * HW + i];
        skey[i] = ((unsigned long long)(~__float_as_uint(s)) << 32) | (unsigned)i;
    }
    __syncthreads();
    for (int k = 2; k <= HW; k <<= 1) {
        for (int j = k >> 1; j > 0; j >>= 1) {
            for (int i = tid; i < HW; i += 1024) {
                int ixj = i ^ j;
                if (ixj > i) {
                    bool up = ((i & k) == 0);
                    unsigned long long a = skey[i], c = skey[ixj];
                    if (up ? (a > c) : (a < c)) { skey[i] = c; skey[ixj] = a; }
                }
            }
            __syncthreads();
        }
    }
    for (int t = tid; t < NMS_CAND; t += 1024) {
        unsigned long long key = skey[t];
        int idx = (int)(unsigned)key;
        float s = __uint_as_float(~(unsigned)(key >> 32));
        int g = b * HW + idx;
        int dst = b * NMS_CAND + t;
        g_cand_sc[dst] = s;
        g_cand_lab[dst] = g_label[g];
        #pragma unroll
        for (int q = 0; q < 4; q++)
            g_cand_box[dst * 4 + q] = g_boxes[(size_t)g * 4 + q];
    }
}

// ---------------- NMS phase A: parallel suppression-bit matrix ----------------
__global__ void nms_mask_k() {
    int i = blockIdx.x;     // candidate row
    int b = blockIdx.y;
    int j = threadIdx.x;    // 1024 threads
    const float* bi = &g_cand_box[(b * NMS_CAND + i) * 4];
    float ix1 = bi[0], iy1 = bi[1], ix2 = bi[2], iy2 = bi[3];
    float ai = fmaxf(ix2 - ix1, 0.f) * fmaxf(iy2 - iy1, 0.f);
    bool pred = false;
    if (j < NMS_CAND && j > i) {
        const float* bj = &g_cand_box[(b * NMS_CAND + j) * 4];
        float aj = fmaxf(bj[2] - bj[0], 0.f) * fmaxf(bj[3] - bj[1], 0.f);
        float xx1 = fmaxf(ix1, bj[0]), yy1 = fmaxf(iy1, bj[1]);
        float xx2 = fminf(ix2, bj[2]), yy2 = fminf(iy2, bj[3]);
        float iw = fmaxf(xx2 - xx1, 0.f), ih = fmaxf(yy2 - yy1, 0.f);
        float inter = iw * ih;
        float iou = inter / (ai + aj - inter + 1e-6f);
        pred = iou > 0.65f;
    }
    unsigned m = __ballot_sync(0xffffffffu, pred);
    if ((j & 31) == 0)
        g_mask[((size_t)(b * NMS_CAND + i)) * 32 + (j >> 5)] = m;
}

// ---------------- NMS phase B: sequential reduce (mask in smem, 1 warp) ----------------
__global__ void nms_reduce_k() {
    extern __shared__ unsigned smask[];   // 1000*32 words = 128000 B
    int b = blockIdx.x;
    for (int t = threadIdx.x; t < NMS_CAND * 32; t += 1024)
        smask[t] = g_mask[(size_t)b * NMS_CAND * 32 + t];
    __syncthreads();
    if (threadIdx.x < 32) {
        int lane = threadIdx.x;
        unsigned removed = 0u;
        for (int i = 0; i < NMS_CAND; i++) {
            unsigned rw = __shfl_sync(0xffffffffu, removed, i >> 5);
            if (!((rw >> (i & 31)) & 1u))
                removed |= smask[i * 32 + lane];
        }
        g_keep[b * 32 + lane] = ~removed;
    }
}

// ---------------- final select: top_k(cand_sc*keep, 100) semantics ----------------
// kept candidates in order (already score-desc), then suppressed (score 0) by index asc.
__global__ void select_k(float* __restrict__ out) {
    __shared__ int ps[1024];
    __shared__ int s_total;
    int b = blockIdx.x;
    int tid = threadIdx.x;
    int kept = 0;
    if (tid < NMS_CAND)
        kept = (g_keep[b * 32 + (tid >> 5)] >> (tid & 31)) & 1;
    ps[tid] = kept;
    __syncthreads();
    for (int off = 1; off < 1024; off <<= 1) {
        int v = (tid >= off) ? ps[tid - off] : 0;
        __syncthreads();
        ps[tid] += v;
        __syncthreads();
    }
    if (tid == 1023) s_total = ps[1023];
    __syncthreads();
    int total = s_total;
    if (tid < NMS_CAND) {
        int excl = ps[tid] - kept;
        int pos = kept ? excl : total + (tid - excl);
        if (pos < MAX_DET) {
            int src = b * NMS_CAND + tid;
            out[(b * MAX_DET + pos) * 4 + 0] = g_cand_box[src * 4 + 0];
            out[(b * MAX_DET + pos) * 4 + 1] = g_cand_box[src * 4 + 1];
            out[(b * MAX_DET + pos) * 4 + 2] = g_cand_box[src * 4 + 2];
            out[(b * MAX_DET + pos) * 4 + 3] = g_cand_box[src * 4 + 3];
            out[BB * MAX_DET * 4 + b * MAX_DET + pos] = kept ? g_cand_sc[src] : 0.f;
            out[BB * MAX_DET * 5 + b * MAX_DET + pos] = (float)g_cand_lab[src];
        }
    }
}

// ---------------- launch ----------------
extern "C" void kernel_launch(void* const* d_in, const int* in_sizes, int n_in,
                              void* d_out, int out_size) {
    (void)in_sizes; (void)n_in; (void)out_size;
    const float* feat = (const float*)d_in[0];
    const float* cls_w_in  = (const float*)d_in[1];
    const float* cls_b_in  = (const float*)d_in[2];
    const float* cls_w_hid = (const float*)d_in[3];
    const float* cls_b_hid = (const float*)d_in[4];
    const float* cls_w_out = (const float*)d_in[5];
    const float* cls_b_out = (const float*)d_in[6];
    const float* obj_w_in  = (const float*)d_in[7];
    const float* obj_b_in  = (const float*)d_in[8];
    const float* obj_w_hid = (const float*)d_in[9];
    const float* obj_b_hid = (const float*)d_in[10];
    const float* obj_w_out = (const float*)d_in[11];
    const float* obj_b_out = (const float*)d_in[12];
    const float* box_w_in  = (const float*)d_in[13];
    const float* box_b_in  = (const float*)d_in[14];
    const float* box_w_hid = (const float*)d_in[15];
    const float* box_b_hid = (const float*)d_in[16];
    const float* box_w_out = (const float*)d_in[17];
    const float* box_b_out = (const float*)d_in[18];
    float* out = (float*)d_out;

    float *X0, *bA, *bB, *cls, *obj, *box;
    cudaGetSymbolAddress((void**)&X0, g_X0);
    cudaGetSymbolAddress((void**)&bA, g_bufA);
    cudaGetSymbolAddress((void**)&bB, g_bufB);
    cudaGetSymbolAddress((void**)&cls, g_cls);
    cudaGetSymbolAddress((void**)&obj, g_obj);
    cudaGetSymbolAddress((void**)&box, g_box);

    cudaFuncSetAttribute(sort_k, cudaFuncAttributeMaxDynamicSharedMemorySize, 131072);
    cudaFuncSetAttribute(nms_reduce_k, cudaFuncAttributeMaxDynamicSharedMemorySize, 131072);

    // 1) pack feat -> pixel-major
    transpose_k<<<dim3(HW / 32, CC / 32, BB), dim3(32, 8)>>>(feat);

    // 2) three heads
    auto run_head = [&](const float* w_in, const float* b_in,
                        const float* w_hid, const float* b_hid,
                        const float* w_out, const float* b_out,
                        int Nout, float* out_buf) {
        dim3 g256(2, MPIX / 128);
        gemm_k<<<g256, 256>>>(X0, w_in, b_in, bA, 256, 256, 0);
        float* cur = bA; float* nxt = bB;
        for (int i = 0; i < 4; i++) {
            gemm_k<<<g256, 256>>>(cur, w_hid + (size_t)i * 256 * 256, b_hid + i * 256,
                                  nxt, 256, 256, 1);
            float* t = cur; cur = nxt; nxt = t;
        }
        dim3 gout((Nout + 127) / 128, MPIX / 128);
        gemm_k<<<gout, 256>>>(cur, w_out, b_out, out_buf, Nout, Nout, 0);
    };
    run_head(cls_w_in, cls_b_in, cls_w_hid, cls_b_hid, cls_w_out, cls_b_out, 81, cls);
    run_head(obj_w_in, obj_b_in, obj_w_hid, obj_b_hid, obj_w_out, obj_b_out, 2, obj);
    run_head(box_w_in, box_b_in, box_w_hid, box_b_hid, box_w_out, box_b_out, 4, box);

    // 3) decode scores/labels/boxes
    decode_k<<<MPIX / 256, 256>>>();

    // 4) per-batch exact top-1000 via full bitonic sort
    sort_k<<<BB, 1024, 131072>>>();

    // 5) NMS
    nms_mask_k<<<dim3(NMS_CAND, BB), 1024>>>();
    nms_reduce_k<<<BB, 1024, NMS_CAND * 32 * (int)sizeof(unsigned)>>>();

    // 6) final top-100 select + output
    select_k<<<BB, 1024>>>(out);
}

// round 3
// speedup vs baseline: 1.1519x; 1.1519x over previous
#include <cuda_runtime.h>
#include <cstdint>
#include <cstddef>

// ---------------- problem constants ----------------
#define BB 2
#define CC 256
#define HH 128
#define WW 128
#define HW 16384
#define MPIX 32768
#define NCLS 80
#define NMS_CAND 1000
#define MAX_DET 100
#define KB 16

// ---------------- scratch ----------------
__device__ float g_X0[(size_t)MPIX * 256];
__device__ float g_bA[3][(size_t)MPIX * 256];   // per-head ping
__device__ float g_bB[3][(size_t)MPIX * 256];   // per-head pong
__device__ float g_score[MPIX];
__device__ int   g_label[MPIX];
__device__ float g_boxes[(size_t)MPIX * 4];
__device__ float g_cand_sc[BB * NMS_CAND];
__device__ int   g_cand_lab[BB * NMS_CAND];
__device__ float g_cand_box[BB * NMS_CAND * 4];
__device__ unsigned g_mask[(size_t)BB * NMS_CAND * 32];
__device__ unsigned g_keep[BB * 32];

// ---------------- cp.async helpers ----------------
__device__ __forceinline__ unsigned smem_addr(const void* p) {
    return (unsigned)__cvta_generic_to_shared(p);
}
__device__ __forceinline__ void cpasync4(unsigned dst, const float* src) {
    asm volatile("cp.async.ca.shared.global [%0], [%1], 4;\n" :: "r"(dst), "l"(src));
}
__device__ __forceinline__ void cp_commit() {
    asm volatile("cp.async.commit_group;\n" ::: "memory");
}
template <int N>
__device__ __forceinline__ void cp_wait() {
    asm volatile("cp.async.wait_group %0;\n" :: "n"(N) : "memory");
}

// ---------------- feat (B,C,H,W) -> X0 [B*HW][C] ----------------
__global__ void transpose_k(const float* __restrict__ feat) {
    __shared__ float t[32][33];
    int hw0 = blockIdx.x * 32;
    int c0  = blockIdx.y * 32;
    int b   = blockIdx.z;
    int tx = threadIdx.x, ty = threadIdx.y;
    #pragma unroll
    for (int i = 0; i < 32; i += 8)
        t[ty + i][tx] = feat[((size_t)(b * CC + c0 + ty + i)) * HW + hw0 + tx];
    __syncthreads();
    #pragma unroll
    for (int i = 0; i < 32; i += 8)
        g_X0[((size_t)(b * HW + hw0 + ty + i)) * 256 + c0 + tx] = t[tx][ty + i];
}

// ---------------- 3-head pipelined fp32 GEMM ----------------
// C_h[m][n] = sum_k A_h[m][k]*W_h[n][k] + bias_h[n] (+A_h[m][n] if residual)
// M=32768, N=K=256. Tiles 128x128, KB=16, 3-stage cp.async pipeline.
// smem per stage: As[16][132], Bs[16][132] (k-major, pad 132 -> 2-way store conflicts only)
#define STG_F (16 * 132)
__global__ void __launch_bounds__(256, 2) gemm3_k(
    const float* __restrict__ A0, const float* __restrict__ A1, const float* __restrict__ A2,
    const float* __restrict__ W0, const float* __restrict__ W1, const float* __restrict__ W2,
    const float* __restrict__ c0, const float* __restrict__ c1, const float* __restrict__ c2,
    float* __restrict__ O0, float* __restrict__ O1, float* __restrict__ O2,
    int residual)
{
    extern __shared__ __align__(16) float sm[];
    float* As = sm;                 // [3][16][132]
    float* Bs = sm + 3 * STG_F;     // [3][16][132]

    const int head = blockIdx.z;
    const float* A    = head == 0 ? A0 : head == 1 ? A1 : A2;
    const float* Wt   = head == 0 ? W0 : head == 1 ? W1 : W2;
    const float* bias = head == 0 ? c0 : head == 1 ? c1 : c2;
    float* Cout       = head == 0 ? O0 : head == 1 ? O1 : O2;

    const int m0 = blockIdx.y * 128;
    const int n0 = blockIdx.x * 128;
    const int tid = threadIdx.x;
    const int tx = tid & 15, ty = tid >> 4;

    const float* Abase = A + (size_t)m0 * 256;
    const float* Bbase = Wt + (size_t)n0 * 256;

    auto load_panel = [&](int p, int s) {
        const float* Ap = Abase + p * KB;
        const float* Bp = Bbase + p * KB;
        float* Asd = As + s * STG_F;
        float* Bsd = Bs + s * STG_F;
        #pragma unroll
        for (int l = 0; l < 8; l++) {
            int idx = tid + l * 256;
            int k = idx & 15, row = idx >> 4;
            cpasync4(smem_addr(&Asd[k * 132 + row]), Ap + (size_t)row * 256 + k);
            cpasync4(smem_addr(&Bsd[k * 132 + row]), Bp + (size_t)row * 256 + k);
        }
        cp_commit();
    };

    float acc[8][8];
    #pragma unroll
    for (int i = 0; i < 8; i++)
        #pragma unroll
        for (int j = 0; j < 8; j++) acc[i][j] = 0.f;

    load_panel(0, 0);
    load_panel(1, 1);

    int s = 0, ls = 2;
    #pragma unroll 1
    for (int p = 0; p < 16; p++) {
        if (p < 14) cp_wait<1>(); else cp_wait<0>();
        __syncthreads();
        if (p + 2 < 16) {
            load_panel(p + 2, ls);
            ls = (ls == 2) ? 0 : ls + 1;
        }
        const float* Asd = As + s * STG_F;
        const float* Bsd = Bs + s * STG_F;
        s = (s == 2) ? 0 : s + 1;
        #pragma unroll
        for (int kk = 0; kk < KB; kk++) {
            float4 a0 = *(const float4*)&Asd[kk * 132 + ty * 8];
            float4 a1 = *(const float4*)&Asd[kk * 132 + ty * 8 + 4];
            float4 b0 = *(const float4*)&Bsd[kk * 132 + tx * 8];
            float4 b1 = *(const float4*)&Bsd[kk * 132 + tx * 8 + 4];
            float a[8] = {a0.x, a0.y, a0.z, a0.w, a1.x, a1.y, a1.z, a1.w};
            float b[8] = {b0.x, b0.y, b0.z, b0.w, b1.x, b1.y, b1.z, b1.w};
            #pragma unroll
            for (int i = 0; i < 8; i++)
                #pragma unroll
                for (int j = 0; j < 8; j++)
                    acc[i][j] = fmaf(a[i], b[j], acc[i][j]);
        }
    }

    #pragma unroll
    for (int i = 0; i < 8; i++) {
        int m = m0 + ty * 8 + i;
        #pragma unroll
        for (int j = 0; j < 8; j++) {
            int n = n0 + tx * 8 + j;
            float v = acc[i][j] + bias[n];
            if (residual) v += A[(size_t)m * 256 + n];
            Cout[(size_t)m * 256 + n] = v;
        }
    }
}

// ---------------- fused out-layers + decode ----------------
// 96 logical columns: 0..79 = cls classes, 80..83 = box ltrb, 84 = obj, 85..95 = pad(0).
// Thread (tx,ty): rows ty*8+i, cols tx+16j (j=0..5). j<5 -> cls input; j==5 -> col 80+tx:
// tx<4 -> box input, tx==4 -> obj input, tx>4 -> pad (zero weights).
__device__ __forceinline__ float sigmoidf_(float x) { return 1.f / (1.f + expf(-x)); }

__global__ void __launch_bounds__(256) outdec_k(
    const float* __restrict__ Acls, const float* __restrict__ Aobj, const float* __restrict__ Abox,
    const float* __restrict__ cw, const float* __restrict__ cb,
    const float* __restrict__ ow, const float* __restrict__ ob,
    const float* __restrict__ bw, const float* __restrict__ bbx)
{
    extern __shared__ __align__(16) float sm[];
    float* As_c = sm;                       // 16*132
    float* As_b = sm + STG_F;               // 16*132
    float* As_o = sm + 2 * STG_F;           // 16*132
    float* Bsw  = sm + 3 * STG_F;           // 16*100
    float* sbias = sm + 3 * STG_F + 1600;   // 96 (pad to 112)
    float* slog = sm + 3 * STG_F + 1712;    // 128*97

    const int m0 = blockIdx.x * 128;
    const int tid = threadIdx.x;
    const int tx = tid & 15, ty = tid >> 4;

    // bias per slot
    if (tid < 96) {
        float bv = 0.f;
        if (tid < 80) bv = cb[tid];
        else if (tid < 84) bv = bbx[tid - 80];
        else if (tid == 84) bv = ob[0];
        sbias[tid] = bv;
    }

    float acc[8][6];
    #pragma unroll
    for (int i = 0; i < 8; i++)
        #pragma unroll
        for (int j = 0; j < 6; j++) acc[i][j] = 0.f;

    #pragma unroll 1
    for (int p = 0; p < 16; p++) {
        __syncthreads();
        // load three A tiles (float4 -> k-major scatter)
        #pragma unroll
        for (int l = 0; l < 2; l++) {
            int idx = tid + l * 256;
            int row = idx >> 2;
            int kc  = (idx & 3) << 2;
            float4 vc = *(const float4*)(Acls + (size_t)(m0 + row) * 256 + p * KB + kc);
            float4 vb = *(const float4*)(Abox + (size_t)(m0 + row) * 256 + p * KB + kc);
            float4 vo = *(const float4*)(Aobj + (size_t)(m0 + row) * 256 + p * KB + kc);
            As_c[(kc + 0) * 132 + row] = vc.x; As_c[(kc + 1) * 132 + row] = vc.y;
            As_c[(kc + 2) * 132 + row] = vc.z; As_c[(kc + 3) * 132 + row] = vc.w;
            As_b[(kc + 0) * 132 + row] = vb.x; As_b[(kc + 1) * 132 + row] = vb.y;
            As_b[(kc + 2) * 132 + row] = vb.z; As_b[(kc + 3) * 132 + row] = vb.w;
            As_o[(kc + 0) * 132 + row] = vo.x; As_o[(kc + 1) * 132 + row] = vo.y;
            As_o[(kc + 2) * 132 + row] = vo.z; As_o[(kc + 3) * 132 + row] = vo.w;
        }
        // load weight tile Bsw[k][s]
        #pragma unroll
        for (int l = 0; l < 6; l++) {
            int idx = tid + l * 256;
            int k = idx & 15, slot = idx >> 4;
            float v = 0.f;
            if (slot < 80)       v = cw[slot * 256 + p * KB + k];
            else if (slot < 84)  v = bw[(slot - 80) * 256 + p * KB + k];
            else if (slot == 84) v = ow[p * KB + k];
            Bsw[k * 100 + slot] = v;
        }
        __syncthreads();

        const float* As_x = (tx < 4) ? As_b : (tx == 4 ? As_o : As_c);
        #pragma unroll
        for (int kk = 0; kk < KB; kk++) {
            float4 a0 = *(const float4*)&As_c[kk * 132 + ty * 8];
            float4 a1 = *(const float4*)&As_c[kk * 132 + ty * 8 + 4];
            float4 x0 = *(const float4*)&As_x[kk * 132 + ty * 8];
            float4 x1 = *(const float4*)&As_x[kk * 132 + ty * 8 + 4];
            float ac[8] = {a0.x, a0.y, a0.z, a0.w, a1.x, a1.y, a1.z, a1.w};
            float ax[8] = {x0.x, x0.y, x0.z, x0.w, x1.x, x1.y, x1.z, x1.w};
            float b[6];
            #pragma unroll
            for (int j = 0; j < 6; j++) b[j] = Bsw[kk * 100 + tx + 16 * j];
            #pragma unroll
            for (int i = 0; i < 8; i++) {
                #pragma unroll
                for (int j = 0; j < 5; j++)
                    acc[i][j] = fmaf(ac[i], b[j], acc[i][j]);
                acc[i][5] = fmaf(ax[i], b[5], acc[i][5]);
            }
        }
    }

    // logits to smem
    __syncthreads();
    #pragma unroll
    for (int i = 0; i < 8; i++)
        #pragma unroll
        for (int j = 0; j < 6; j++) {
            int col = tx + 16 * j;
            slog[(ty * 8 + i) * 97 + col] = acc[i][j] + sbias[col];
        }
    __syncthreads();

    if (tid < 128) {
        const float* lg = &slog[tid * 97];
        float objp = sigmoidf_(lg[84]);
        float best = -1.f; int bl = 0;
        #pragma unroll 4
        for (int c = 0; c < NCLS; c++) {
            float pr = sigmoidf_(lg[c]) * objp;
            if (pr > best) { best = pr; bl = c; }
        }
        int n = m0 + tid;
        g_score[n] = best;
        g_label[n] = bl;
        int hw = n & (HW - 1);
        int h = hw >> 7, w = hw & 127;
        float px = (w + 0.5f) * 8.f;
        float py = (h + 0.5f) * 8.f;
        float l = expf(lg[80]) * 8.f;
        float t = expf(lg[81]) * 8.f;
        float r = expf(lg[82]) * 8.f;
        float d = expf(lg[83]) * 8.f;
        g_boxes[(size_t)n * 4 + 0] = px - l;
        g_boxes[(size_t)n * 4 + 1] = py - t;
        g_boxes[(size_t)n * 4 + 2] = px + r;
        g_boxes[(size_t)n * 4 + 3] = py + d;
    }
}

// ---------------- per-batch full bitonic sort (exact top-1000) ----------------
__global__ void sort_k() {
    extern __shared__ unsigned long long skey[];
    int b = blockIdx.x;
    int tid = threadIdx.x;
    for (int i = tid; i < HW; i += 1024) {
        float s = g_score[b * HW + i];
        skey[i] = ((unsigned long long)(~__float_as_uint(s)) << 32) | (unsigned)i;
    }
    __syncthreads();
    for (int k = 2; k <= HW; k <<= 1) {
        for (int j = k >> 1; j > 0; j >>= 1) {
            for (int i = tid; i < HW; i += 1024) {
                int ixj = i ^ j;
                if (ixj > i) {
                    bool up = ((i & k) == 0);
                    unsigned long long a = skey[i], c = skey[ixj];
                    if (up ? (a > c) : (a < c)) { skey[i] = c; skey[ixj] = a; }
                }
            }
            __syncthreads();
        }
    }
    for (int t = tid; t < NMS_CAND; t += 1024) {
        unsigned long long key = skey[t];
        int idx = (int)(unsigned)key;
        float s = __uint_as_float(~(unsigned)(key >> 32));
        int g = b * HW + idx;
        int dst = b * NMS_CAND + t;
        g_cand_sc[dst] = s;
        g_cand_lab[dst] = g_label[g];
        #pragma unroll
        for (int q = 0; q < 4; q++)
            g_cand_box[dst * 4 + q] = g_boxes[(size_t)g * 4 + q];
    }
}

// ---------------- NMS ----------------
__global__ void nms_mask_k() {
    int i = blockIdx.x;
    int b = blockIdx.y;
    int j = threadIdx.x;
    const float* bi = &g_cand_box[(b * NMS_CAND + i) * 4];
    float ix1 = bi[0], iy1 = bi[1], ix2 = bi[2], iy2 = bi[3];
    float ai = fmaxf(ix2 - ix1, 0.f) * fmaxf(iy2 - iy1, 0.f);
    bool pred = false;
    if (j < NMS_CAND && j > i) {
        const float* bj = &g_cand_box[(b * NMS_CAND + j) * 4];
        float aj = fmaxf(bj[2] - bj[0], 0.f) * fmaxf(bj[3] - bj[1], 0.f);
        float xx1 = fmaxf(ix1, bj[0]), yy1 = fmaxf(iy1, bj[1]);
        float xx2 = fminf(ix2, bj[2]), yy2 = fminf(iy2, bj[3]);
        float iw = fmaxf(xx2 - xx1, 0.f), ih = fmaxf(yy2 - yy1, 0.f);
        float inter = iw * ih;
        float iou = inter / (ai + aj - inter + 1e-6f);
        pred = iou > 0.65f;
    }
    unsigned m = __ballot_sync(0xffffffffu, pred);
    if ((j & 31) == 0)
        g_mask[((size_t)(b * NMS_CAND + i)) * 32 + (j >> 5)] = m;
}

__global__ void nms_reduce_k() {
    extern __shared__ unsigned smask[];
    int b = blockIdx.x;
    for (int t = threadIdx.x; t < NMS_CAND * 32; t += 1024)
        smask[t] = g_mask[(size_t)b * NMS_CAND * 32 + t];
    __syncthreads();
    if (threadIdx.x < 32) {
        int lane = threadIdx.x;
        unsigned removed = 0u;
        for (int i = 0; i < NMS_CAND; i++) {
            unsigned rw = __shfl_sync(0xffffffffu, removed, i >> 5);
            if (!((rw >> (i & 31)) & 1u))
                removed |= smask[i * 32 + lane];
        }
        g_keep[b * 32 + lane] = ~removed;
    }
}

// ---------------- final select ----------------
__global__ void select_k(float* __restrict__ out) {
    __shared__ int ps[1024];
    __shared__ int s_total;
    int b = blockIdx.x;
    int tid = threadIdx.x;
    int kept = 0;
    if (tid < NMS_CAND)
        kept = (g_keep[b * 32 + (tid >> 5)] >> (tid & 31)) & 1;
    ps[tid] = kept;
    __syncthreads();
    for (int off = 1; off < 1024; off <<= 1) {
        int v = (tid >= off) ? ps[tid - off] : 0;
        __syncthreads();
        ps[tid] += v;
        __syncthreads();
    }
    if (tid == 1023) s_total = ps[1023];
    __syncthreads();
    int total = s_total;
    if (tid < NMS_CAND) {
        int excl = ps[tid] - kept;
        int pos = kept ? excl : total + (tid - excl);
        if (pos < MAX_DET) {
            int src = b * NMS_CAND + tid;
            out[(b * MAX_DET + pos) * 4 + 0] = g_cand_box[src * 4 + 0];
            out[(b * MAX_DET + pos) * 4 + 1] = g_cand_box[src * 4 + 1];
            out[(b * MAX_DET + pos) * 4 + 2] = g_cand_box[src * 4 + 2];
            out[(b * MAX_DET + pos) * 4 + 3] = g_cand_box[src * 4 + 3];
            out[BB * MAX_DET * 4 + b * MAX_DET + pos] = kept ? g_cand_sc[src] : 0.f;
            out[BB * MAX_DET * 5 + b * MAX_DET + pos] = (float)g_cand_lab[src];
        }
    }
}

// ---------------- launch ----------------
extern "C" void kernel_launch(void* const* d_in, const int* in_sizes, int n_in,
                              void* d_out, int out_size) {
    (void)in_sizes; (void)n_in; (void)out_size;
    const float* feat = (const float*)d_in[0];
    const float* cls_w_in  = (const float*)d_in[1];
    const float* cls_b_in  = (const float*)d_in[2];
    const float* cls_w_hid = (const float*)d_in[3];
    const float* cls_b_hid = (const float*)d_in[4];
    const float* cls_w_out = (const float*)d_in[5];
    const float* cls_b_out = (const float*)d_in[6];
    const float* obj_w_in  = (const float*)d_in[7];
    const float* obj_b_in  = (const float*)d_in[8];
    const float* obj_w_hid = (const float*)d_in[9];
    const float* obj_b_hid = (const float*)d_in[10];
    const float* obj_w_out = (const float*)d_in[11];
    const float* obj_b_out = (const float*)d_in[12];
    const float* box_w_in  = (const float*)d_in[13];
    const float* box_b_in  = (const float*)d_in[14];
    const float* box_w_hid = (const float*)d_in[15];
    const float* box_b_hid = (const float*)d_in[16];
    const float* box_w_out = (const float*)d_in[17];
    const float* box_b_out = (const float*)d_in[18];
    float* out = (float*)d_out;

    float *X0, *bA, *bB;
    cudaGetSymbolAddress((void**)&X0, g_X0);
    cudaGetSymbolAddress((void**)&bA, g_bA);
    cudaGetSymbolAddress((void**)&bB, g_bB);
    const size_t HS = (size_t)MPIX * 256;
    float* A[3] = {bA, bA + HS, bA + 2 * HS};
    float* Bt[3] = {bB, bB + HS, bB + 2 * HS};

    const int gemm_smem = 6 * STG_F * (int)sizeof(float);          // 50688 B
    const int outdec_smem = (3 * STG_F + 1712 + 128 * 97) * (int)sizeof(float);
    cudaFuncSetAttribute(gemm3_k, cudaFuncAttributeMaxDynamicSharedMemorySize, gemm_smem);
    cudaFuncSetAttribute(outdec_k, cudaFuncAttributeMaxDynamicSharedMemorySize, outdec_smem);
    cudaFuncSetAttribute(sort_k, cudaFuncAttributeMaxDynamicSharedMemorySize, 131072);
    cudaFuncSetAttribute(nms_reduce_k, cudaFuncAttributeMaxDynamicSharedMemorySize, 131072);

    // 1) pack feat -> pixel-major
    transpose_k<<<dim3(HW / 32, CC / 32, BB), dim3(32, 8)>>>(feat);

    // 2) input layers (all 3 heads, one launch)
    dim3 gg(2, MPIX / 128, 3);
    gemm3_k<<<gg, 256, gemm_smem>>>(X0, X0, X0,
                                    cls_w_in, obj_w_in, box_w_in,
                                    cls_b_in, obj_b_in, box_b_in,
                                    A[0], A[1], A[2], 0);
    // 3) hidden layers: A->B->A->B->A
    float* cur[3] = {A[0], A[1], A[2]};
    float* nxt[3] = {Bt[0], Bt[1], Bt[2]};
    for (int i = 0; i < 4; i++) {
        gemm3_k<<<gg, 256, gemm_smem>>>(cur[0], cur[1], cur[2],
                                        cls_w_hid + (size_t)i * 65536,
                                        obj_w_hid + (size_t)i * 65536,
                                        box_w_hid + (size_t)i * 65536,
                                        cls_b_hid + i * 256,
                                        obj_b_hid + i * 256,
                                        box_b_hid + i * 256,
                                        nxt[0], nxt[1], nxt[2], 1);
        for (int h = 0; h < 3; h++) { float* t = cur[h]; cur[h] = nxt[h]; nxt[h] = t; }
    }

    // 4) fused out-layers + decode
    outdec_k<<<MPIX / 128, 256, outdec_smem>>>(cur[0], cur[1], cur[2],
                                               cls_w_out, cls_b_out,
                                               obj_w_out, obj_b_out,
                                               box_w_out, box_b_out);

    // 5) exact per-batch top-1000
    sort_k<<<BB, 1024, 131072>>>();

    // 6) NMS
    nms_mask_k<<<dim3(NMS_CAND, BB), 1024>>>();
    nms_reduce_k<<<BB, 1024, NMS_CAND * 32 * (int)sizeof(unsigned)>>>();

    // 7) final top-100 select
    select_k<<<BB, 1024>>>(out);
}

// round 4
// speedup vs baseline: 1.3222x; 1.1478x over previous
#include <cuda_runtime.h>
#include <cstdint>
#include <cstddef>

// ---------------- problem constants ----------------
#define BB 2
#define CC 256
#define HH 128
#define WW 128
#define HW 16384
#define MPIX 32768
#define NCLS 80
#define NMS_CAND 1000
#define MAX_DET 100
#define KB 32
#define STG (KB * 132)     // floats per stage per array

// ---------------- scratch ----------------
__device__ float g_X0[(size_t)MPIX * 256];
__device__ float g_bA[3][(size_t)MPIX * 256];
__device__ float g_bB[3][(size_t)MPIX * 256];
__device__ float g_score[MPIX];
__device__ int   g_label[MPIX];
__device__ float g_boxes[(size_t)MPIX * 4];
__device__ float g_cand_sc[BB * NMS_CAND];
__device__ int   g_cand_lab[BB * NMS_CAND];
__device__ float g_cand_box[BB * NMS_CAND * 4];
__device__ unsigned g_mask[(size_t)BB * NMS_CAND * 32];
__device__ unsigned g_keep[BB * 32];

// ---------------- helpers ----------------
__device__ __forceinline__ unsigned smem_addr(const void* p) {
    return (unsigned)__cvta_generic_to_shared(p);
}
__device__ __forceinline__ void cpasync4(unsigned dst, const float* src) {
    asm volatile("cp.async.ca.shared.global [%0], [%1], 4;\n" :: "r"(dst), "l"(src));
}
__device__ __forceinline__ void cp_commit() {
    asm volatile("cp.async.commit_group;\n" ::: "memory");
}
template <int N>
__device__ __forceinline__ void cp_wait() {
    asm volatile("cp.async.wait_group %0;\n" :: "n"(N) : "memory");
}
// packed dual-fp32 FMA (rn rounding, bit-identical to two scalar fmaf)
__device__ __forceinline__ void ffma2(unsigned long long& d, unsigned long long a, unsigned long long b) {
    asm("fma.rn.f32x2 %0, %1, %2, %0;" : "+l"(d) : "l"(a), "l"(b));
}
__device__ __forceinline__ unsigned long long dup2(float x) {
    unsigned long long r;
    asm("mov.b64 %0, {%1, %1};" : "=l"(r) : "f"(x));
    return r;
}
__device__ __forceinline__ void unpack2(unsigned long long v, float& lo, float& hi) {
    asm("mov.b64 {%0, %1}, %2;" : "=f"(lo), "=f"(hi) : "l"(v));
}

// ---------------- feat (B,C,H,W) -> X0 [B*HW][C] ----------------
__global__ void transpose_k(const float* __restrict__ feat) {
    __shared__ float t[32][33];
    int hw0 = blockIdx.x * 32;
    int c0  = blockIdx.y * 32;
    int b   = blockIdx.z;
    int tx = threadIdx.x, ty = threadIdx.y;
    #pragma unroll
    for (int i = 0; i < 32; i += 8)
        t[ty + i][tx] = feat[((size_t)(b * CC + c0 + ty + i)) * HW + hw0 + tx];
    __syncthreads();
    #pragma unroll
    for (int i = 0; i < 32; i += 8)
        g_X0[((size_t)(b * HW + hw0 + ty + i)) * 256 + c0 + tx] = t[tx][ty + i];
}

// ---------------- 3-head fp32 GEMM, f32x2 packed inner loop ----------------
// C_h[m][n] = sum_k A_h[m][k]*W_h[n][k] + bias_h[n] (+A_h[m][n] if residual)
// 128x128 tile, 256 threads, per-thread 8x8 (as 8x4 f32x2 pairs), KB=32, 2-stage cp.async.
__global__ void __launch_bounds__(256, 2) gemm3_k(
    const float* __restrict__ A0, const float* __restrict__ A1, const float* __restrict__ A2,
    const float* __restrict__ W0, const float* __restrict__ W1, const float* __restrict__ W2,
    const float* __restrict__ c0, const float* __restrict__ c1, const float* __restrict__ c2,
    float* __restrict__ O0, float* __restrict__ O1, float* __restrict__ O2,
    int residual)
{
    extern __shared__ __align__(16) float sm[];
    float* As = sm;              // [2][KB][132]
    float* Bs = sm + 2 * STG;    // [2][KB][132]

    const int head = blockIdx.z;
    const float* A    = head == 0 ? A0 : head == 1 ? A1 : A2;
    const float* Wt   = head == 0 ? W0 : head == 1 ? W1 : W2;
    const float* bias = head == 0 ? c0 : head == 1 ? c1 : c2;
    float* Cout       = head == 0 ? O0 : head == 1 ? O1 : O2;

    const int m0 = blockIdx.y * 128;
    const int n0 = blockIdx.x * 128;
    const int tid = threadIdx.x;
    const int tx = tid & 15, ty = tid >> 4;

    const float* Abase = A + (size_t)m0 * 256;
    const float* Bbase = Wt + (size_t)n0 * 256;

    auto load_panel = [&](int p, int s) {
        const float* Ap = Abase + p * KB;
        const float* Bp = Bbase + p * KB;
        float* Asd = As + s * STG;
        float* Bsd = Bs + s * STG;
        #pragma unroll
        for (int l = 0; l < 16; l++) {
            int idx = tid + l * 256;
            int k = idx & 31, row = idx >> 5;
            cpasync4(smem_addr(&Asd[k * 132 + row]), Ap + (size_t)row * 256 + k);
            cpasync4(smem_addr(&Bsd[k * 132 + row]), Bp + (size_t)row * 256 + k);
        }
        cp_commit();
    };

    unsigned long long acc2[8][4];
    #pragma unroll
    for (int i = 0; i < 8; i++)
        #pragma unroll
        for (int j = 0; j < 4; j++) acc2[i][j] = 0ull;

    load_panel(0, 0);

    int s = 0;
    #pragma unroll 1
    for (int p = 0; p < 256 / KB; p++) {
        cp_wait<0>();
        __syncthreads();
        if (p + 1 < 256 / KB) load_panel(p + 1, s ^ 1);
        const float* Asd = As + s * STG;
        const float* Bsd = Bs + s * STG;
        s ^= 1;
        #pragma unroll 8
        for (int kk = 0; kk < KB; kk++) {
            float4 a0 = *(const float4*)&Asd[kk * 132 + ty * 8];
            float4 a1 = *(const float4*)&Asd[kk * 132 + ty * 8 + 4];
            ulonglong2 bb0 = *(const ulonglong2*)&Bsd[kk * 132 + tx * 8];
            ulonglong2 bb1 = *(const ulonglong2*)&Bsd[kk * 132 + tx * 8 + 4];
            unsigned long long b2[4] = {bb0.x, bb0.y, bb1.x, bb1.y};
            unsigned long long a2[8] = {dup2(a0.x), dup2(a0.y), dup2(a0.z), dup2(a0.w),
                                        dup2(a1.x), dup2(a1.y), dup2(a1.z), dup2(a1.w)};
            #pragma unroll
            for (int i = 0; i < 8; i++)
                #pragma unroll
                for (int j = 0; j < 4; j++)
                    ffma2(acc2[i][j], a2[i], b2[j]);
        }
    }

    #pragma unroll
    for (int i = 0; i < 8; i++) {
        int m = m0 + ty * 8 + i;
        #pragma unroll
        for (int j = 0; j < 4; j++) {
            int n = n0 + tx * 8 + 2 * j;
            float lo, hi;
            unpack2(acc2[i][j], lo, hi);
            float vlo = lo + bias[n];
            float vhi = hi + bias[n + 1];
            if (residual) {
                vlo += A[(size_t)m * 256 + n];
                vhi += A[(size_t)m * 256 + n + 1];
            }
            *(float2*)&Cout[(size_t)m * 256 + n] = make_float2(vlo, vhi);
        }
    }
}

// ---------------- fused out-layers + decode (unchanged from R3, passed) ----------------
#define STG16 (16 * 132)
__device__ __forceinline__ float sigmoidf_(float x) { return 1.f / (1.f + expf(-x)); }

__global__ void __launch_bounds__(256) outdec_k(
    const float* __restrict__ Acls, const float* __restrict__ Aobj, const float* __restrict__ Abox,
    const float* __restrict__ cw, const float* __restrict__ cb,
    const float* __restrict__ ow, const float* __restrict__ ob,
    const float* __restrict__ bw, const float* __restrict__ bbx)
{
    extern __shared__ __align__(16) float sm[];
    float* As_c = sm;
    float* As_b = sm + STG16;
    float* As_o = sm + 2 * STG16;
    float* Bsw  = sm + 3 * STG16;
    float* sbias = sm + 3 * STG16 + 1600;
    float* slog = sm + 3 * STG16 + 1712;

    const int m0 = blockIdx.x * 128;
    const int tid = threadIdx.x;
    const int tx = tid & 15, ty = tid >> 4;

    if (tid < 96) {
        float bv = 0.f;
        if (tid < 80) bv = cb[tid];
        else if (tid < 84) bv = bbx[tid - 80];
        else if (tid == 84) bv = ob[0];
        sbias[tid] = bv;
    }

    float acc[8][6];
    #pragma unroll
    for (int i = 0; i < 8; i++)
        #pragma unroll
        for (int j = 0; j < 6; j++) acc[i][j] = 0.f;

    #pragma unroll 1
    for (int p = 0; p < 16; p++) {
        __syncthreads();
        #pragma unroll
        for (int l = 0; l < 2; l++) {
            int idx = tid + l * 256;
            int row = idx >> 2;
            int kc  = (idx & 3) << 2;
            float4 vc = *(const float4*)(Acls + (size_t)(m0 + row) * 256 + p * 16 + kc);
            float4 vb = *(const float4*)(Abox + (size_t)(m0 + row) * 256 + p * 16 + kc);
            float4 vo = *(const float4*)(Aobj + (size_t)(m0 + row) * 256 + p * 16 + kc);
            As_c[(kc + 0) * 132 + row] = vc.x; As_c[(kc + 1) * 132 + row] = vc.y;
            As_c[(kc + 2) * 132 + row] = vc.z; As_c[(kc + 3) * 132 + row] = vc.w;
            As_b[(kc + 0) * 132 + row] = vb.x; As_b[(kc + 1) * 132 + row] = vb.y;
            As_b[(kc + 2) * 132 + row] = vb.z; As_b[(kc + 3) * 132 + row] = vb.w;
            As_o[(kc + 0) * 132 + row] = vo.x; As_o[(kc + 1) * 132 + row] = vo.y;
            As_o[(kc + 2) * 132 + row] = vo.z; As_o[(kc + 3) * 132 + row] = vo.w;
        }
        #pragma unroll
        for (int l = 0; l < 6; l++) {
            int idx = tid + l * 256;
            int k = idx & 15, slot = idx >> 4;
            float v = 0.f;
            if (slot < 80)       v = cw[slot * 256 + p * 16 + k];
            else if (slot < 84)  v = bw[(slot - 80) * 256 + p * 16 + k];
            else if (slot == 84) v = ow[p * 16 + k];
            Bsw[k * 100 + slot] = v;
        }
        __syncthreads();

        const float* As_x = (tx < 4) ? As_b : (tx == 4 ? As_o : As_c);
        #pragma unroll
        for (int kk = 0; kk < 16; kk++) {
            float4 a0 = *(const float4*)&As_c[kk * 132 + ty * 8];
            float4 a1 = *(const float4*)&As_c[kk * 132 + ty * 8 + 4];
            float4 x0 = *(const float4*)&As_x[kk * 132 + ty * 8];
            float4 x1 = *(const float4*)&As_x[kk * 132 + ty * 8 + 4];
            float ac[8] = {a0.x, a0.y, a0.z, a0.w, a1.x, a1.y, a1.z, a1.w};
            float ax[8] = {x0.x, x0.y, x0.z, x0.w, x1.x, x1.y, x1.z, x1.w};
            float b[6];
            #pragma unroll
            for (int j = 0; j < 6; j++) b[j] = Bsw[kk * 100 + tx + 16 * j];
            #pragma unroll
            for (int i = 0; i < 8; i++) {
                #pragma unroll
                for (int j = 0; j < 5; j++)
                    acc[i][j] = fmaf(ac[i], b[j], acc[i][j]);
                acc[i][5] = fmaf(ax[i], b[5], acc[i][5]);
            }
        }
    }

    __syncthreads();
    #pragma unroll
    for (int i = 0; i < 8; i++)
        #pragma unroll
        for (int j = 0; j < 6; j++) {
            int col = tx + 16 * j;
            slog[(ty * 8 + i) * 97 + col] = acc[i][j] + sbias[col];
        }
    __syncthreads();

    if (tid < 128) {
        const float* lg = &slog[tid * 97];
        float objp = sigmoidf_(lg[84]);
        float best = -1.f; int bl = 0;
        #pragma unroll 4
        for (int c = 0; c < NCLS; c++) {
            float pr = sigmoidf_(lg[c]) * objp;
            if (pr > best) { best = pr; bl = c; }
        }
        int n = m0 + tid;
        g_score[n] = best;
        g_label[n] = bl;
        int hw = n & (HW - 1);
        int h = hw >> 7, w = hw & 127;
        float px = (w + 0.5f) * 8.f;
        float py = (h + 0.5f) * 8.f;
        float l = expf(lg[80]) * 8.f;
        float t = expf(lg[81]) * 8.f;
        float r = expf(lg[82]) * 8.f;
        float d = expf(lg[83]) * 8.f;
        g_boxes[(size_t)n * 4 + 0] = px - l;
        g_boxes[(size_t)n * 4 + 1] = py - t;
        g_boxes[(size_t)n * 4 + 2] = px + r;
        g_boxes[(size_t)n * 4 + 3] = py + d;
    }
}

// ---------------- exact top-1000: 2-level histogram select + compact + bitonic 4096 ----------------
// Same key as before: (~score_bits << 32) | idx  -> ascending == (score desc, idx asc).
// Superset compaction at a 16-bit score prefix boundary keeps selection exact.
__global__ void topk_k() {
    __shared__ int hist[256];
    __shared__ int s_b1, s_n1, s_thr, s_cnt;
    __shared__ unsigned long long skey[4096];
    int b = blockIdx.x;
    int tid = threadIdx.x;   // 1024

    if (tid < 256) hist[tid] = 0;
    __syncthreads();
    for (int i = tid; i < HW; i += 1024) {
        unsigned u = __float_as_uint(g_score[b * HW + i]);
        atomicAdd(&hist[u >> 24], 1);
    }
    __syncthreads();
    if (tid == 0) {
        int acc = 0; int bin = 255;
        for (; bin > 0; bin--) { if (acc + hist[bin] >= NMS_CAND) break; acc += hist[bin]; }
        s_b1 = bin; s_n1 = acc;
    }
    __syncthreads();
    int b1 = s_b1, n1 = s_n1;
    if (tid < 256) hist[tid] = 0;
    __syncthreads();
    for (int i = tid; i < HW; i += 1024) {
        unsigned u = __float_as_uint(g_score[b * HW + i]);
        if ((int)(u >> 24) == b1) atomicAdd(&hist[(u >> 16) & 255], 1);
    }
    __syncthreads();
    if (tid == 0) {
        int acc = n1; int bin = 255;
        for (; bin > 0; bin--) { if (acc + hist[bin] >= NMS_CAND) break; acc += hist[bin]; }
        s_thr = (b1 << 8) | bin;
        s_cnt = 0;
    }
    __syncthreads();
    unsigned thr = (unsigned)s_thr;
    for (int i = tid; i < HW; i += 1024) {
        unsigned u = __float_as_uint(g_score[b * HW + i]);
        if ((u >> 16) >= thr) {
            int pos = atomicAdd(&s_cnt, 1);
            if (pos < 4096)
                skey[pos] = ((unsigned long long)(~u) << 32) | (unsigned)i;
        }
    }
    __syncthreads();
    int cnt = s_cnt < 4096 ? s_cnt : 4096;
    for (int i = tid; i < 4096; i += 1024)
        if (i >= cnt) skey[i] = 0xFFFFFFFFFFFFFFFFull;
    __syncthreads();

    for (int k = 2; k <= 4096; k <<= 1) {
        for (int j = k >> 1; j > 0; j >>= 1) {
            #pragma unroll
            for (int l = 0; l < 4; l++) {
                int i = tid + l * 1024;
                int ixj = i ^ j;
                if (ixj > i) {
                    bool up = ((i & k) == 0);
                    unsigned long long a = skey[i], c = skey[ixj];
                    if (up ? (a > c) : (a < c)) { skey[i] = c; skey[ixj] = a; }
                }
            }
            __syncthreads();
        }
    }

    if (tid < NMS_CAND) {
        unsigned long long key = skey[tid];
        int idx = (int)(unsigned)key;
        float s = __uint_as_float(~(unsigned)(key >> 32));
        int g = b * HW + idx;
        int dst = b * NMS_CAND + tid;
        g_cand_sc[dst] = s;
        g_cand_lab[dst] = g_label[g];
        #pragma unroll
        for (int q = 0; q < 4; q++)
            g_cand_box[dst * 4 + q] = g_boxes[(size_t)g * 4 + q];
    }
}

// ---------------- NMS ----------------
__global__ void nms_mask_k() {
    int i = blockIdx.x;
    int b = blockIdx.y;
    int j = threadIdx.x;
    const float* bi = &g_cand_box[(b * NMS_CAND + i) * 4];
    float ix1 = bi[0], iy1 = bi[1], ix2 = bi[2], iy2 = bi[3];
    float ai = fmaxf(ix2 - ix1, 0.f) * fmaxf(iy2 - iy1, 0.f);
    bool pred = false;
    if (j < NMS_CAND && j > i) {
        const float* bj = &g_cand_box[(b * NMS_CAND + j) * 4];
        float aj = fmaxf(bj[2] - bj[0], 0.f) * fmaxf(bj[3] - bj[1], 0.f);
        float xx1 = fmaxf(ix1, bj[0]), yy1 = fmaxf(iy1, bj[1]);
        float xx2 = fminf(ix2, bj[2]), yy2 = fminf(iy2, bj[3]);
        float iw = fmaxf(xx2 - xx1, 0.f), ih = fmaxf(yy2 - yy1, 0.f);
        float inter = iw * ih;
        float iou = inter / (ai + aj - inter + 1e-6f);
        pred = iou > 0.65f;
    }
    unsigned m = __ballot_sync(0xffffffffu, pred);
    if ((j & 31) == 0)
        g_mask[((size_t)(b * NMS_CAND + i)) * 32 + (j >> 5)] = m;
}

__global__ void nms_reduce_k() {
    extern __shared__ unsigned smask[];
    int b = blockIdx.x;
    for (int t = threadIdx.x; t < NMS_CAND * 32; t += 1024)
        smask[t] = g_mask[(size_t)b * NMS_CAND * 32 + t];
    __syncthreads();
    if (threadIdx.x < 32) {
        int lane = threadIdx.x;
        unsigned removed = 0u;
        for (int i = 0; i < NMS_CAND; i++) {
            unsigned rw = __shfl_sync(0xffffffffu, removed, i >> 5);
            if (!((rw >> (i & 31)) & 1u))
                removed |= smask[i * 32 + lane];
        }
        g_keep[b * 32 + lane] = ~removed;
    }
}

// ---------------- final select ----------------
__global__ void select_k(float* __restrict__ out) {
    __shared__ int ps[1024];
    __shared__ int s_total;
    int b = blockIdx.x;
    int tid = threadIdx.x;
    int kept = 0;
    if (tid < NMS_CAND)
        kept = (g_keep[b * 32 + (tid >> 5)] >> (tid & 31)) & 1;
    ps[tid] = kept;
    __syncthreads();
    for (int off = 1; off < 1024; off <<= 1) {
        int v = (tid >= off) ? ps[tid - off] : 0;
        __syncthreads();
        ps[tid] += v;
        __syncthreads();
    }
    if (tid == 1023) s_total = ps[1023];
    __syncthreads();
    int total = s_total;
    if (tid < NMS_CAND) {
        int excl = ps[tid] - kept;
        int pos = kept ? excl : total + (tid - excl);
        if (pos < MAX_DET) {
            int src = b * NMS_CAND + tid;
            out[(b * MAX_DET + pos) * 4 + 0] = g_cand_box[src * 4 + 0];
            out[(b * MAX_DET + pos) * 4 + 1] = g_cand_box[src * 4 + 1];
            out[(b * MAX_DET + pos) * 4 + 2] = g_cand_box[src * 4 + 2];
            out[(b * MAX_DET + pos) * 4 + 3] = g_cand_box[src * 4 + 3];
            out[BB * MAX_DET * 4 + b * MAX_DET + pos] = kept ? g_cand_sc[src] : 0.f;
            out[BB * MAX_DET * 5 + b * MAX_DET + pos] = (float)g_cand_lab[src];
        }
    }
}

// ---------------- launch ----------------
extern "C" void kernel_launch(void* const* d_in, const int* in_sizes, int n_in,
                              void* d_out, int out_size) {
    (void)in_sizes; (void)n_in; (void)out_size;
    const float* feat = (const float*)d_in[0];
    const float* cls_w_in  = (const float*)d_in[1];
    const float* cls_b_in  = (const float*)d_in[2];
    const float* cls_w_hid = (const float*)d_in[3];
    const float* cls_b_hid = (const float*)d_in[4];
    const float* cls_w_out = (const float*)d_in[5];
    const float* cls_b_out = (const float*)d_in[6];
    const float* obj_w_in  = (const float*)d_in[7];
    const float* obj_b_in  = (const float*)d_in[8];
    const float* obj_w_hid = (const float*)d_in[9];
    const float* obj_b_hid = (const float*)d_in[10];
    const float* obj_w_out = (const float*)d_in[11];
    const float* obj_b_out = (const float*)d_in[12];
    const float* box_w_in  = (const float*)d_in[13];
    const float* box_b_in  = (const float*)d_in[14];
    const float* box_w_hid = (const float*)d_in[15];
    const float* box_b_hid = (const float*)d_in[16];
    const float* box_w_out = (const float*)d_in[17];
    const float* box_b_out = (const float*)d_in[18];
    float* out = (float*)d_out;

    float *X0, *bA, *bB;
    cudaGetSymbolAddress((void**)&X0, g_X0);
    cudaGetSymbolAddress((void**)&bA, g_bA);
    cudaGetSymbolAddress((void**)&bB, g_bB);
    const size_t HS = (size_t)MPIX * 256;
    float* A[3] = {bA, bA + HS, bA + 2 * HS};
    float* Bt[3] = {bB, bB + HS, bB + 2 * HS};

    const int gemm_smem = 4 * STG * (int)sizeof(float);            // 67584 B
    const int outdec_smem = (3 * STG16 + 1712 + 128 * 97) * (int)sizeof(float);
    cudaFuncSetAttribute(gemm3_k, cudaFuncAttributeMaxDynamicSharedMemorySize, gemm_smem);
    cudaFuncSetAttribute(outdec_k, cudaFuncAttributeMaxDynamicSharedMemorySize, outdec_smem);
    cudaFuncSetAttribute(nms_reduce_k, cudaFuncAttributeMaxDynamicSharedMemorySize, 131072);

    // 1) pack feat -> pixel-major
    transpose_k<<<dim3(HW / 32, CC / 32, BB), dim3(32, 8)>>>(feat);

    // 2) input layers (3 heads, one launch)
    dim3 gg(2, MPIX / 128, 3);
    gemm3_k<<<gg, 256, gemm_smem>>>(X0, X0, X0,
                                    cls_w_in, obj_w_in, box_w_in,
                                    cls_b_in, obj_b_in, box_b_in,
                                    A[0], A[1], A[2], 0);
    // 3) hidden layers
    float* cur[3] = {A[0], A[1], A[2]};
    float* nxt[3] = {Bt[0], Bt[1], Bt[2]};
    for (int i = 0; i < 4; i++) {
        gemm3_k<<<gg, 256, gemm_smem>>>(cur[0], cur[1], cur[2],
                                        cls_w_hid + (size_t)i * 65536,
                                        obj_w_hid + (size_t)i * 65536,
                                        box_w_hid + (size_t)i * 65536,
                                        cls_b_hid + i * 256,
                                        obj_b_hid + i * 256,
                                        box_b_hid + i * 256,
                                        nxt[0], nxt[1], nxt[2], 1);
        for (int h = 0; h < 3; h++) { float* t = cur[h]; cur[h] = nxt[h]; nxt[h] = t; }
    }

    // 4) fused out-layers + decode
    outdec_k<<<MPIX / 128, 256, outdec_smem>>>(cur[0], cur[1], cur[2],
                                               cls_w_out, cls_b_out,
                                               obj_w_out, obj_b_out,
                                               box_w_out, box_b_out);

    // 5) exact per-batch top-1000 (histogram select + small sort)
    topk_k<<<BB, 1024>>>();

    // 6) NMS
    nms_mask_k<<<dim3(NMS_CAND, BB), 1024>>>();
    nms_reduce_k<<<BB, 1024, NMS_CAND * 32 * (int)sizeof(unsigned)>>>();

    // 7) final top-100 select
    select_k<<<BB, 1024>>>(out);
}

// round 5
// speedup vs baseline: 1.6317x; 1.2341x over previous
#include <cuda_runtime.h>
#include <cstdint>
#include <cstddef>

// ---------------- problem constants ----------------
#define BB 2
#define CC 256
#define HH 128
#define WW 128
#define HW 16384
#define MPIX 32768
#define NCLS 80
#define NMS_CAND 1000
#define MAX_DET 100
#define KB 32
#define STG (KB * 132)     // floats per stage per array

// ---------------- scratch ----------------
// activations kept TRANSPOSED: [256][MPIX]
__device__ float g_X0[(size_t)CC * MPIX];
__device__ float g_bA[3][(size_t)CC * MPIX];
__device__ float g_bB[3][(size_t)CC * MPIX];
__device__ float g_WT[15 * 256 * 256];          // pre-transposed weights [k][n]
__device__ float g_score[MPIX];
__device__ int   g_label[MPIX];
__device__ float g_boxes[(size_t)MPIX * 4];
__device__ float g_cand_sc[BB * NMS_CAND];
__device__ int   g_cand_lab[BB * NMS_CAND];
__device__ float g_cand_box[BB * NMS_CAND * 4];
__device__ unsigned g_mask[(size_t)BB * NMS_CAND * 32];
__device__ unsigned g_keep[BB * 32];

// ---------------- helpers ----------------
__device__ __forceinline__ unsigned smem_addr(const void* p) {
    return (unsigned)__cvta_generic_to_shared(p);
}
__device__ __forceinline__ void cpasync16(unsigned dst, const float* src) {
    asm volatile("cp.async.cg.shared.global [%0], [%1], 16;\n" :: "r"(dst), "l"(src));
}
__device__ __forceinline__ void cp_commit() {
    asm volatile("cp.async.commit_group;\n" ::: "memory");
}
template <int N>
__device__ __forceinline__ void cp_wait() {
    asm volatile("cp.async.wait_group %0;\n" :: "n"(N) : "memory");
}
__device__ __forceinline__ void ffma2(unsigned long long& d, unsigned long long a, unsigned long long b) {
    asm("fma.rn.f32x2 %0, %1, %2, %0;" : "+l"(d) : "l"(a), "l"(b));
}
__device__ __forceinline__ unsigned long long dup2(float x) {
    unsigned long long r;
    asm("mov.b64 %0, {%1, %1};" : "=l"(r) : "f"(x));
    return r;
}
__device__ __forceinline__ void unpack2(unsigned long long v, float& lo, float& hi) {
    asm("mov.b64 {%0, %1}, %2;" : "=f"(lo), "=f"(hi) : "l"(v));
}

// ---------------- feat (B,C,HW) -> X0T [C][B*HW] (pure strided copy) ----------------
__global__ void x0t_k(const float* __restrict__ feat) {
    int r = blockIdx.x;            // 0..511
    int c = r & 255, b = r >> 8;
    const float4* src = (const float4*)(feat + (size_t)(b * CC + c) * HW);
    float4* dst = (float4*)(g_X0 + (size_t)c * MPIX + b * HW);
    for (int i = threadIdx.x; i < HW / 4; i += 256) dst[i] = src[i];
}

// ---------------- weight transpose: W[n][k] -> WT[k][n], 15 matrices ----------------
__global__ void wtrans_k(const float* __restrict__ cwin, const float* __restrict__ owin,
                         const float* __restrict__ bwin, const float* __restrict__ cwh,
                         const float* __restrict__ owh, const float* __restrict__ bwh) {
    __shared__ float t[32][33];
    int z = blockIdx.z;
    const float* src;
    if (z < 3) src = z == 0 ? cwin : (z == 1 ? owin : bwin);
    else {
        int h = (z - 3) >> 2, li = (z - 3) & 3;
        const float* hh = h == 0 ? cwh : (h == 1 ? owh : bwh);
        src = hh + (size_t)li * 65536;
    }
    float* dst = g_WT + (size_t)z * 65536;
    int x0 = blockIdx.x * 32, y0 = blockIdx.y * 32;
    int tx = threadIdx.x, ty = threadIdx.y;   // (32,8)
    #pragma unroll
    for (int i = 0; i < 32; i += 8)
        t[ty + i][tx] = src[(size_t)(y0 + ty + i) * 256 + x0 + tx];
    __syncthreads();
    #pragma unroll
    for (int i = 0; i < 32; i += 8)
        dst[(size_t)(x0 + ty + i) * 256 + y0 + tx] = t[tx][ty + i];
}

// ---------------- 3-head fp32 GEMM on transposed operands ----------------
// A: [256][MPIX] (k-major activations), W: [256][256] (k-major weights)
// O[n][m] = sum_k A[k][m]*W[k][n] + bias[n] (+A_res[n][m] if residual)
// tile 128(m) x 128(n), KB=32, 2-stage 16B cp.async, f32x2 inner loop.
__global__ void __launch_bounds__(256, 2) gemm3_k(
    const float* __restrict__ A0, const float* __restrict__ A1, const float* __restrict__ A2,
    const float* __restrict__ W0, const float* __restrict__ W1, const float* __restrict__ W2,
    const float* __restrict__ c0, const float* __restrict__ c1, const float* __restrict__ c2,
    float* __restrict__ O0, float* __restrict__ O1, float* __restrict__ O2,
    int residual)
{
    extern __shared__ __align__(16) float sm[];
    float* As = sm;              // [2][KB][132]
    float* Bs = sm + 2 * STG;    // [2][KB][132]

    const int head = blockIdx.z;
    const float* A    = head == 0 ? A0 : head == 1 ? A1 : A2;
    const float* Wt   = head == 0 ? W0 : head == 1 ? W1 : W2;
    const float* bias = head == 0 ? c0 : head == 1 ? c1 : c2;
    float* Cout       = head == 0 ? O0 : head == 1 ? O1 : O2;

    const int m0 = blockIdx.y * 128;
    const int n0 = blockIdx.x * 128;
    const int tid = threadIdx.x;
    const int tx = tid & 15, ty = tid >> 4;

    auto load_panel = [&](int p, int s) {
        float* Asd = As + s * STG;
        float* Bsd = Bs + s * STG;
        #pragma unroll
        for (int l = 0; l < 4; l++) {
            int idx = tid + l * 256;
            int k = idx >> 5, c4 = idx & 31;
            cpasync16(smem_addr(&Asd[k * 132 + c4 * 4]),
                      A + (size_t)(p * KB + k) * MPIX + m0 + c4 * 4);
        }
        #pragma unroll
        for (int l = 0; l < 4; l++) {
            int idx = tid + l * 256;
            int k = idx >> 5, c4 = idx & 31;
            cpasync16(smem_addr(&Bsd[k * 132 + c4 * 4]),
                      Wt + (size_t)(p * KB + k) * 256 + n0 + c4 * 4);
        }
        cp_commit();
    };

    unsigned long long acc2[8][4];   // [n-slot][m-pair]
    #pragma unroll
    for (int j = 0; j < 8; j++)
        #pragma unroll
        for (int q = 0; q < 4; q++) acc2[j][q] = 0ull;

    load_panel(0, 0);

    int s = 0;
    #pragma unroll 1
    for (int p = 0; p < 256 / KB; p++) {
        cp_wait<0>();
        __syncthreads();
        if (p + 1 < 256 / KB) load_panel(p + 1, s ^ 1);
        const float* Asd = As + s * STG;
        const float* Bsd = Bs + s * STG;
        s ^= 1;
        #pragma unroll 8
        for (int kk = 0; kk < KB; kk++) {
            ulonglong2 aA = *(const ulonglong2*)&Asd[kk * 132 + 4 * ty];        // m: 4ty..4ty+3
            ulonglong2 aB = *(const ulonglong2*)&Asd[kk * 132 + 64 + 4 * ty];   // m: 64+4ty..
            float4 bb0 = *(const float4*)&Bsd[kk * 132 + 4 * tx];               // n: 4tx..4tx+3
            float4 bb1 = *(const float4*)&Bsd[kk * 132 + 64 + 4 * tx];          // n: 64+4tx..
            unsigned long long am[4] = {aA.x, aA.y, aB.x, aB.y};
            unsigned long long bd[8] = {dup2(bb0.x), dup2(bb0.y), dup2(bb0.z), dup2(bb0.w),
                                        dup2(bb1.x), dup2(bb1.y), dup2(bb1.z), dup2(bb1.w)};
            #pragma unroll
            for (int j = 0; j < 8; j++)
                #pragma unroll
                for (int q = 0; q < 4; q++)
                    ffma2(acc2[j][q], am[q], bd[j]);
        }
    }

    // epilogue: write O[n][m] (transposed), residual read also [n][m]
    #pragma unroll
    for (int j = 0; j < 8; j++) {
        int n = n0 + ((j < 4) ? (4 * tx + j) : (64 + 4 * tx + (j - 4)));
        float bv = bias[n];
        float f0, f1, f2, f3, h0, h1, h2, h3;
        unpack2(acc2[j][0], f0, f1);
        unpack2(acc2[j][1], f2, f3);
        unpack2(acc2[j][2], h0, h1);
        unpack2(acc2[j][3], h2, h3);
        float4 v0 = make_float4(f0 + bv, f1 + bv, f2 + bv, f3 + bv);
        float4 v1 = make_float4(h0 + bv, h1 + bv, h2 + bv, h3 + bv);
        if (residual) {
            float4 r0 = *(const float4*)(A + (size_t)n * MPIX + m0 + 4 * ty);
            float4 r1 = *(const float4*)(A + (size_t)n * MPIX + m0 + 64 + 4 * ty);
            v0.x += r0.x; v0.y += r0.y; v0.z += r0.z; v0.w += r0.w;
            v1.x += r1.x; v1.y += r1.y; v1.z += r1.z; v1.w += r1.w;
        }
        *(float4*)(Cout + (size_t)n * MPIX + m0 + 4 * ty) = v0;
        *(float4*)(Cout + (size_t)n * MPIX + m0 + 64 + 4 * ty) = v1;
    }
}

// ---------------- fused out-layers + decode (A sources now transposed) ----------------
#define STG16 (16 * 132)
__device__ __forceinline__ float sigmoidf_(float x) { return 1.f / (1.f + expf(-x)); }

__global__ void __launch_bounds__(256) outdec_k(
    const float* __restrict__ Acls, const float* __restrict__ Aobj, const float* __restrict__ Abox,
    const float* __restrict__ cw, const float* __restrict__ cb,
    const float* __restrict__ ow, const float* __restrict__ ob,
    const float* __restrict__ bw, const float* __restrict__ bbx)
{
    extern __shared__ __align__(16) float sm[];
    float* As_c = sm;
    float* As_b = sm + STG16;
    float* As_o = sm + 2 * STG16;
    float* Bsw  = sm + 3 * STG16;
    float* sbias = sm + 3 * STG16 + 1600;
    float* slog = sm + 3 * STG16 + 1712;

    const int m0 = blockIdx.x * 128;
    const int tid = threadIdx.x;
    const int tx = tid & 15, ty = tid >> 4;

    if (tid < 96) {
        float bv = 0.f;
        if (tid < 80) bv = cb[tid];
        else if (tid < 84) bv = bbx[tid - 80];
        else if (tid == 84) bv = ob[0];
        sbias[tid] = bv;
    }

    float acc[8][6];
    #pragma unroll
    for (int i = 0; i < 8; i++)
        #pragma unroll
        for (int j = 0; j < 6; j++) acc[i][j] = 0.f;

    #pragma unroll 1
    for (int p = 0; p < 16; p++) {
        __syncthreads();
        // A tiles: k-major gmem -> k-major smem, straight float4 copies
        #pragma unroll
        for (int l = 0; l < 2; l++) {
            int idx = tid + l * 256;
            int k = idx >> 5, c4 = idx & 31;
            size_t off = (size_t)(p * 16 + k) * MPIX + m0 + c4 * 4;
            *(float4*)&As_c[k * 132 + c4 * 4] = *(const float4*)(Acls + off);
            *(float4*)&As_b[k * 132 + c4 * 4] = *(const float4*)(Abox + off);
            *(float4*)&As_o[k * 132 + c4 * 4] = *(const float4*)(Aobj + off);
        }
        #pragma unroll
        for (int l = 0; l < 6; l++) {
            int idx = tid + l * 256;
            int k = idx & 15, slot = idx >> 4;
            float v = 0.f;
            if (slot < 80)       v = cw[slot * 256 + p * 16 + k];
            else if (slot < 84)  v = bw[(slot - 80) * 256 + p * 16 + k];
            else if (slot == 84) v = ow[p * 16 + k];
            Bsw[k * 100 + slot] = v;
        }
        __syncthreads();

        const float* As_x = (tx < 4) ? As_b : (tx == 4 ? As_o : As_c);
        #pragma unroll
        for (int kk = 0; kk < 16; kk++) {
            float4 a0 = *(const float4*)&As_c[kk * 132 + ty * 8];
            float4 a1 = *(const float4*)&As_c[kk * 132 + ty * 8 + 4];
            float4 x0 = *(const float4*)&As_x[kk * 132 + ty * 8];
            float4 x1 = *(const float4*)&As_x[kk * 132 + ty * 8 + 4];
            float ac[8] = {a0.x, a0.y, a0.z, a0.w, a1.x, a1.y, a1.z, a1.w};
            float ax[8] = {x0.x, x0.y, x0.z, x0.w, x1.x, x1.y, x1.z, x1.w};
            float b[6];
            #pragma unroll
            for (int j = 0; j < 6; j++) b[j] = Bsw[kk * 100 + tx + 16 * j];
            #pragma unroll
            for (int i = 0; i < 8; i++) {
                #pragma unroll
                for (int j = 0; j < 5; j++)
                    acc[i][j] = fmaf(ac[i], b[j], acc[i][j]);
                acc[i][5] = fmaf(ax[i], b[5], acc[i][5]);
            }
        }
    }

    __syncthreads();
    #pragma unroll
    for (int i = 0; i < 8; i++)
        #pragma unroll
        for (int j = 0; j < 6; j++) {
            int col = tx + 16 * j;
            slog[(ty * 8 + i) * 97 + col] = acc[i][j] + sbias[col];
        }
    __syncthreads();

    if (tid < 128) {
        const float* lg = &slog[tid * 97];
        float objp = sigmoidf_(lg[84]);
        float best = -1.f; int bl = 0;
        #pragma unroll 4
        for (int c = 0; c < NCLS; c++) {
            float pr = sigmoidf_(lg[c]) * objp;
            if (pr > best) { best = pr; bl = c; }
        }
        int n = m0 + tid;
        g_score[n] = best;
        g_label[n] = bl;
        int hw = n & (HW - 1);
        int h = hw >> 7, w = hw & 127;
        float px = (w + 0.5f) * 8.f;
        float py = (h + 0.5f) * 8.f;
        float l = expf(lg[80]) * 8.f;
        float t = expf(lg[81]) * 8.f;
        float r = expf(lg[82]) * 8.f;
        float d = expf(lg[83]) * 8.f;
        g_boxes[(size_t)n * 4 + 0] = px - l;
        g_boxes[(size_t)n * 4 + 1] = py - t;
        g_boxes[(size_t)n * 4 + 2] = px + r;
        g_boxes[(size_t)n * 4 + 3] = py + d;
    }
}

// ---------------- exact top-1000: histogram select + compact + bitonic 4096 ----------------
__global__ void topk_k() {
    __shared__ int hist[256];
    __shared__ int s_b1, s_n1, s_thr, s_cnt;
    __shared__ unsigned long long skey[4096];
    int b = blockIdx.x;
    int tid = threadIdx.x;   // 1024

    if (tid < 256) hist[tid] = 0;
    __syncthreads();
    for (int i = tid; i < HW; i += 1024) {
        unsigned u = __float_as_uint(g_score[b * HW + i]);
        atomicAdd(&hist[u >> 24], 1);
    }
    __syncthreads();
    if (tid == 0) {
        int acc = 0; int bin = 255;
        for (; bin > 0; bin--) { if (acc + hist[bin] >= NMS_CAND) break; acc += hist[bin]; }
        s_b1 = bin; s_n1 = acc;
    }
    __syncthreads();
    int b1 = s_b1, n1 = s_n1;
    if (tid < 256) hist[tid] = 0;
    __syncthreads();
    for (int i = tid; i < HW; i += 1024) {
        unsigned u = __float_as_uint(g_score[b * HW + i]);
        if ((int)(u >> 24) == b1) atomicAdd(&hist[(u >> 16) & 255], 1);
    }
    __syncthreads();
    if (tid == 0) {
        int acc = n1; int bin = 255;
        for (; bin > 0; bin--) { if (acc + hist[bin] >= NMS_CAND) break; acc += hist[bin]; }
        s_thr = (b1 << 8) | bin;
        s_cnt = 0;
    }
    __syncthreads();
    unsigned thr = (unsigned)s_thr;
    for (int i = tid; i < HW; i += 1024) {
        unsigned u = __float_as_uint(g_score[b * HW + i]);
        if ((u >> 16) >= thr) {
            int pos = atomicAdd(&s_cnt, 1);
            if (pos < 4096)
                skey[pos] = ((unsigned long long)(~u) << 32) | (unsigned)i;
        }
    }
    __syncthreads();
    int cnt = s_cnt < 4096 ? s_cnt : 4096;
    for (int i = tid; i < 4096; i += 1024)
        if (i >= cnt) skey[i] = 0xFFFFFFFFFFFFFFFFull;
    __syncthreads();

    for (int k = 2; k <= 4096; k <<= 1) {
        for (int j = k >> 1; j > 0; j >>= 1) {
            #pragma unroll
            for (int l = 0; l < 4; l++) {
                int i = tid + l * 1024;
                int ixj = i ^ j;
                if (ixj > i) {
                    bool up = ((i & k) == 0);
                    unsigned long long a = skey[i], c = skey[ixj];
                    if (up ? (a > c) : (a < c)) { skey[i] = c; skey[ixj] = a; }
                }
            }
            __syncthreads();
        }
    }

    if (tid < NMS_CAND) {
        unsigned long long key = skey[tid];
        int idx = (int)(unsigned)key;
        float s = __uint_as_float(~(unsigned)(key >> 32));
        int g = b * HW + idx;
        int dst = b * NMS_CAND + tid;
        g_cand_sc[dst] = s;
        g_cand_lab[dst] = g_label[g];
        #pragma unroll
        for (int q = 0; q < 4; q++)
            g_cand_box[dst * 4 + q] = g_boxes[(size_t)g * 4 + q];
    }
}

// ---------------- NMS ----------------
__global__ void nms_mask_k() {
    int i = blockIdx.x;
    int b = blockIdx.y;
    int j = threadIdx.x;
    const float* bi = &g_cand_box[(b * NMS_CAND + i) * 4];
    float ix1 = bi[0], iy1 = bi[1], ix2 = bi[2], iy2 = bi[3];
    float ai = fmaxf(ix2 - ix1, 0.f) * fmaxf(iy2 - iy1, 0.f);
    bool pred = false;
    if (j < NMS_CAND && j > i) {
        const float* bj = &g_cand_box[(b * NMS_CAND + j) * 4];
        float aj = fmaxf(bj[2] - bj[0], 0.f) * fmaxf(bj[3] - bj[1], 0.f);
        float xx1 = fmaxf(ix1, bj[0]), yy1 = fmaxf(iy1, bj[1]);
        float xx2 = fminf(ix2, bj[2]), yy2 = fminf(iy2, bj[3]);
        float iw = fmaxf(xx2 - xx1, 0.f), ih = fmaxf(yy2 - yy1, 0.f);
        float inter = iw * ih;
        float iou = inter / (ai + aj - inter + 1e-6f);
        pred = iou > 0.65f;
    }
    unsigned m = __ballot_sync(0xffffffffu, pred);
    if ((j & 31) == 0)
        g_mask[((size_t)(b * NMS_CAND + i)) * 32 + (j >> 5)] = m;
}

__global__ void nms_reduce_k() {
    extern __shared__ unsigned smask[];
    int b = blockIdx.x;
    for (int t = threadIdx.x; t < NMS_CAND * 32; t += 1024)
        smask[t] = g_mask[(size_t)b * NMS_CAND * 32 + t];
    __syncthreads();
    if (threadIdx.x < 32) {
        int lane = threadIdx.x;
        unsigned removed = 0u;
        for (int i = 0; i < NMS_CAND; i++) {
            unsigned rw = __shfl_sync(0xffffffffu, removed, i >> 5);
            if (!((rw >> (i & 31)) & 1u))
                removed |= smask[i * 32 + lane];
        }
        g_keep[b * 32 + lane] = ~removed;
    }
}

// ---------------- final select ----------------
__global__ void select_k(float* __restrict__ out) {
    __shared__ int ps[1024];
    __shared__ int s_total;
    int b = blockIdx.x;
    int tid = threadIdx.x;
    int kept = 0;
    if (tid < NMS_CAND)
        kept = (g_keep[b * 32 + (tid >> 5)] >> (tid & 31)) & 1;
    ps[tid] = kept;
    __syncthreads();
    for (int off = 1; off < 1024; off <<= 1) {
        int v = (tid >= off) ? ps[tid - off] : 0;
        __syncthreads();
        ps[tid] += v;
        __syncthreads();
    }
    if (tid == 1023) s_total = ps[1023];
    __syncthreads();
    int total = s_total;
    if (tid < NMS_CAND) {
        int excl = ps[tid] - kept;
        int pos = kept ? excl : total + (tid - excl);
        if (pos < MAX_DET) {
            int src = b * NMS_CAND + tid;
            out[(b * MAX_DET + pos) * 4 + 0] = g_cand_box[src * 4 + 0];
            out[(b * MAX_DET + pos) * 4 + 1] = g_cand_box[src * 4 + 1];
            out[(b * MAX_DET + pos) * 4 + 2] = g_cand_box[src * 4 + 2];
            out[(b * MAX_DET + pos) * 4 + 3] = g_cand_box[src * 4 + 3];
            out[BB * MAX_DET * 4 + b * MAX_DET + pos] = kept ? g_cand_sc[src] : 0.f;
            out[BB * MAX_DET * 5 + b * MAX_DET + pos] = (float)g_cand_lab[src];
        }
    }
}

// ---------------- launch ----------------
extern "C" void kernel_launch(void* const* d_in, const int* in_sizes, int n_in,
                              void* d_out, int out_size) {
    (void)in_sizes; (void)n_in; (void)out_size;
    const float* feat = (const float*)d_in[0];
    const float* cls_w_in  = (const float*)d_in[1];
    const float* cls_b_in  = (const float*)d_in[2];
    const float* cls_w_hid = (const float*)d_in[3];
    const float* cls_b_hid = (const float*)d_in[4];
    const float* cls_w_out = (const float*)d_in[5];
    const float* cls_b_out = (const float*)d_in[6];
    const float* obj_w_in  = (const float*)d_in[7];
    const float* obj_b_in  = (const float*)d_in[8];
    const float* obj_w_hid = (const float*)d_in[9];
    const float* obj_b_hid = (const float*)d_in[10];
    const float* obj_w_out = (const float*)d_in[11];
    const float* obj_b_out = (const float*)d_in[12];
    const float* box_w_in  = (const float*)d_in[13];
    const float* box_b_in  = (const float*)d_in[14];
    const float* box_w_hid = (const float*)d_in[15];
    const float* box_b_hid = (const float*)d_in[16];
    const float* box_w_out = (const float*)d_in[17];
    const float* box_b_out = (const float*)d_in[18];
    float* out = (float*)d_out;

    float *X0, *bA, *bB, *WT;
    cudaGetSymbolAddress((void**)&X0, g_X0);
    cudaGetSymbolAddress((void**)&bA, g_bA);
    cudaGetSymbolAddress((void**)&bB, g_bB);
    cudaGetSymbolAddress((void**)&WT, g_WT);
    const size_t HS = (size_t)CC * MPIX;
    float* A[3] = {bA, bA + HS, bA + 2 * HS};
    float* Bt[3] = {bB, bB + HS, bB + 2 * HS};

    const int gemm_smem = 4 * STG * (int)sizeof(float);   // 67584 B
    const int outdec_smem = (3 * STG16 + 1712 + 128 * 97) * (int)sizeof(float);
    cudaFuncSetAttribute(gemm3_k, cudaFuncAttributeMaxDynamicSharedMemorySize, gemm_smem);
    cudaFuncSetAttribute(outdec_k, cudaFuncAttributeMaxDynamicSharedMemorySize, outdec_smem);
    cudaFuncSetAttribute(nms_reduce_k, cudaFuncAttributeMaxDynamicSharedMemorySize, 131072);

    // 0) prologue: pack feat (pure copy) + transpose all 15 weight matrices
    x0t_k<<<512, 256>>>(feat);
    wtrans_k<<<dim3(8, 8, 15), dim3(32, 8)>>>(cls_w_in, obj_w_in, box_w_in,
                                              cls_w_hid, obj_w_hid, box_w_hid);

    // WT layout: z 0..2 = in (cls,obj,box); z 3+h*4+i = hid layer i of head h
    auto wt_in  = [&](int h) { return WT + (size_t)h * 65536; };
    auto wt_hid = [&](int h, int i) { return WT + (size_t)(3 + h * 4 + i) * 65536; };

    // 1) input layers
    dim3 gg(2, MPIX / 128, 3);
    gemm3_k<<<gg, 256, gemm_smem>>>(X0, X0, X0,
                                    wt_in(0), wt_in(1), wt_in(2),
                                    cls_b_in, obj_b_in, box_b_in,
                                    A[0], A[1], A[2], 0);
    // 2) hidden layers
    float* cur[3] = {A[0], A[1], A[2]};
    float* nxt[3] = {Bt[0], Bt[1], Bt[2]};
    for (int i = 0; i < 4; i++) {
        gemm3_k<<<gg, 256, gemm_smem>>>(cur[0], cur[1], cur[2],
                                        wt_hid(0, i), wt_hid(1, i), wt_hid(2, i),
                                        cls_b_hid + i * 256,
                                        obj_b_hid + i * 256,
                                        box_b_hid + i * 256,
                                        nxt[0], nxt[1], nxt[2], 1);
        for (int h = 0; h < 3; h++) { float* t = cur[h]; cur[h] = nxt[h]; nxt[h] = t; }
    }

    // 3) fused out-layers + decode
    outdec_k<<<MPIX / 128, 256, outdec_smem>>>(cur[0], cur[1], cur[2],
                                               cls_w_out, cls_b_out,
                                               obj_w_out, obj_b_out,
                                               box_w_out, box_b_out);

    // 4) exact per-batch top-1000
    topk_k<<<BB, 1024>>>();

    // 5) NMS
    nms_mask_k<<<dim3(NMS_CAND, BB), 1024>>>();
    nms_reduce_k<<<BB, 1024, NMS_CAND * 32 * (int)sizeof(unsigned)>>>();

    // 6) final top-100 select
    select_k<<<BB, 1024>>>(out);
}

// round 7
// speedup vs baseline: 1.6335x; 1.0011x over previous
#include <cuda_runtime.h>
#include <cstdint>
#include <cstddef>

// ---------------- problem constants ----------------
#define BB 2
#define CC 256
#define HH 128
#define WW 128
#define HW 16384
#define MPIX 32768
#define NCLS 80
#define NMS_CAND 1000
#define MAX_DET 100
#define KB 32
#define STG (KB * 132)     // floats per stage per array
#define NPANEL (256 / KB)  // 8

// ---------------- scratch ----------------
// activations kept TRANSPOSED: [256][MPIX]
__device__ float g_X0[(size_t)CC * MPIX];
__device__ float g_bA[3][(size_t)CC * MPIX];
__device__ float g_bB[3][(size_t)CC * MPIX];
__device__ float g_WT[15 * 256 * 256];          // pre-transposed weights [k][n]
__device__ float g_score[MPIX];
__device__ int   g_label[MPIX];
__device__ float g_boxes[(size_t)MPIX * 4];
__device__ float g_cand_sc[BB * NMS_CAND];
__device__ int   g_cand_lab[BB * NMS_CAND];
__device__ float g_cand_box[BB * NMS_CAND * 4];
__device__ unsigned g_mask[(size_t)BB * NMS_CAND * 32];
__device__ unsigned g_keep[BB * 32];

// ---------------- helpers ----------------
__device__ __forceinline__ unsigned smem_addr(const void* p) {
    return (unsigned)__cvta_generic_to_shared(p);
}
__device__ __forceinline__ void cpasync16(unsigned dst, const float* src) {
    asm volatile("cp.async.cg.shared.global [%0], [%1], 16;\n" :: "r"(dst), "l"(src));
}
__device__ __forceinline__ void cp_commit() {
    asm volatile("cp.async.commit_group;\n" ::: "memory");
}
template <int N>
__device__ __forceinline__ void cp_wait() {
    asm volatile("cp.async.wait_group %0;\n" :: "n"(N) : "memory");
}
__device__ __forceinline__ void ffma2(unsigned long long& d, unsigned long long a, unsigned long long b) {
    asm("fma.rn.f32x2 %0, %1, %2, %0;" : "+l"(d) : "l"(a), "l"(b));
}
__device__ __forceinline__ unsigned long long dup2(float x) {
    unsigned long long r;
    asm("mov.b64 %0, {%1, %1};" : "=l"(r) : "f"(x));
    return r;
}
__device__ __forceinline__ void unpack2(unsigned long long v, float& lo, float& hi) {
    asm("mov.b64 {%0, %1}, %2;" : "=f"(lo), "=f"(hi) : "l"(v));
}

// ---------------- feat (B,C,HW) -> X0T [C][B*HW] (pure strided copy) ----------------
__global__ void x0t_k(const float* __restrict__ feat) {
    int r = blockIdx.x;            // 0..511
    int c = r & 255, b = r >> 8;
    const float4* src = (const float4*)(feat + (size_t)(b * CC + c) * HW);
    float4* dst = (float4*)(g_X0 + (size_t)c * MPIX + b * HW);
    for (int i = threadIdx.x; i < HW / 4; i += 256) dst[i] = src[i];
}

// ---------------- weight transpose: W[n][k] -> WT[k][n], 15 matrices ----------------
__global__ void wtrans_k(const float* __restrict__ cwin, const float* __restrict__ owin,
                         const float* __restrict__ bwin, const float* __restrict__ cwh,
                         const float* __restrict__ owh, const float* __restrict__ bwh) {
    __shared__ float t[32][33];
    int z = blockIdx.z;
    const float* src;
    if (z < 3) src = z == 0 ? cwin : (z == 1 ? owin : bwin);
    else {
        int h = (z - 3) >> 2, li = (z - 3) & 3;
        const float* hh = h == 0 ? cwh : (h == 1 ? owh : bwh);
        src = hh + (size_t)li * 65536;
    }
    float* dst = g_WT + (size_t)z * 65536;
    int x0 = blockIdx.x * 32, y0 = blockIdx.y * 32;
    int tx = threadIdx.x, ty = threadIdx.y;   // (32,8)
    #pragma unroll
    for (int i = 0; i < 32; i += 8)
        t[ty + i][tx] = src[(size_t)(y0 + ty + i) * 256 + x0 + tx];
    __syncthreads();
    #pragma unroll
    for (int i = 0; i < 32; i += 8)
        dst[(size_t)(x0 + ty + i) * 256 + y0 + tx] = t[tx][ty + i];
}

// ---------------- 3-head fp32 GEMM, transposed operands, 3-stage pipeline ----------------
// A: [256][MPIX] (k-major activations), W: [256][256] (k-major weights)
// O[n][m] = sum_k A[k][m]*W[k][n] + bias[n] (+A_res[n][m] if residual)
__global__ void __launch_bounds__(256, 2) gemm3_k(
    const float* __restrict__ A0, const float* __restrict__ A1, const float* __restrict__ A2,
    const float* __restrict__ W0, const float* __restrict__ W1, const float* __restrict__ W2,
    const float* __restrict__ c0, const float* __restrict__ c1, const float* __restrict__ c2,
    float* __restrict__ O0, float* __restrict__ O1, float* __restrict__ O2,
    int residual)
{
    extern __shared__ __align__(16) float sm[];
    float* As = sm;              // [3][KB][132]
    float* Bs = sm + 3 * STG;    // [3][KB][132]

    const int head = blockIdx.z;
    const float* A    = head == 0 ? A0 : head == 1 ? A1 : A2;
    const float* Wt   = head == 0 ? W0 : head == 1 ? W1 : W2;
    const float* bias = head == 0 ? c0 : head == 1 ? c1 : c2;
    float* Cout       = head == 0 ? O0 : head == 1 ? O1 : O2;

    const int m0 = blockIdx.y * 128;
    const int n0 = blockIdx.x * 128;
    const int tid = threadIdx.x;
    const int tx = tid & 15, ty = tid >> 4;

    auto load_panel = [&](int p, int s) {
        float* Asd = As + s * STG;
        float* Bsd = Bs + s * STG;
        #pragma unroll
        for (int l = 0; l < 4; l++) {
            int idx = tid + l * 256;
            int k = idx >> 5, c4 = idx & 31;
            cpasync16(smem_addr(&Asd[k * 132 + c4 * 4]),
                      A + (size_t)(p * KB + k) * MPIX + m0 + c4 * 4);
        }
        #pragma unroll
        for (int l = 0; l < 4; l++) {
            int idx = tid + l * 256;
            int k = idx >> 5, c4 = idx & 31;
            cpasync16(smem_addr(&Bsd[k * 132 + c4 * 4]),
                      Wt + (size_t)(p * KB + k) * 256 + n0 + c4 * 4);
        }
        cp_commit();
    };

    unsigned long long acc2[8][4];   // [n-slot][m-pair]
    #pragma unroll
    for (int j = 0; j < 8; j++)
        #pragma unroll
        for (int q = 0; q < 4; q++) acc2[j][q] = 0ull;

    load_panel(0, 0);
    load_panel(1, 1);

    #pragma unroll 1
    for (int p = 0; p < NPANEL; p++) {
        if (p < NPANEL - 1) cp_wait<1>(); else cp_wait<0>();
        __syncthreads();
        if (p + 2 < NPANEL) load_panel(p + 2, (p + 2) % 3);
        const float* Asd = As + (p % 3) * STG;
        const float* Bsd = Bs + (p % 3) * STG;
        #pragma unroll 8
        for (int kk = 0; kk < KB; kk++) {
            ulonglong2 aA = *(const ulonglong2*)&Asd[kk * 132 + 4 * ty];        // m: 4ty..4ty+3
            ulonglong2 aB = *(const ulonglong2*)&Asd[kk * 132 + 64 + 4 * ty];   // m: 64+4ty..
            float4 bb0 = *(const float4*)&Bsd[kk * 132 + 4 * tx];               // n: 4tx..4tx+3
            float4 bb1 = *(const float4*)&Bsd[kk * 132 + 64 + 4 * tx];          // n: 64+4tx..
            unsigned long long am[4] = {aA.x, aA.y, aB.x, aB.y};
            unsigned long long bd[8] = {dup2(bb0.x), dup2(bb0.y), dup2(bb0.z), dup2(bb0.w),
                                        dup2(bb1.x), dup2(bb1.y), dup2(bb1.z), dup2(bb1.w)};
            #pragma unroll
            for (int j = 0; j < 8; j++)
                #pragma unroll
                for (int q = 0; q < 4; q++)
                    ffma2(acc2[j][q], am[q], bd[j]);
        }
    }

    // epilogue: write O[n][m] (transposed), residual read also [n][m]
    #pragma unroll
    for (int j = 0; j < 8; j++) {
        int n = n0 + ((j < 4) ? (4 * tx + j) : (64 + 4 * tx + (j - 4)));
        float bv = bias[n];
        float f0, f1, f2, f3, h0, h1, h2, h3;
        unpack2(acc2[j][0], f0, f1);
        unpack2(acc2[j][1], f2, f3);
        unpack2(acc2[j][2], h0, h1);
        unpack2(acc2[j][3], h2, h3);
        float4 v0 = make_float4(f0 + bv, f1 + bv, f2 + bv, f3 + bv);
        float4 v1 = make_float4(h0 + bv, h1 + bv, h2 + bv, h3 + bv);
        if (residual) {
            float4 r0 = *(const float4*)(A + (size_t)n * MPIX + m0 + 4 * ty);
            float4 r1 = *(const float4*)(A + (size_t)n * MPIX + m0 + 64 + 4 * ty);
            v0.x += r0.x; v0.y += r0.y; v0.z += r0.z; v0.w += r0.w;
            v1.x += r1.x; v1.y += r1.y; v1.z += r1.z; v1.w += r1.w;
        }
        *(float4*)(Cout + (size_t)n * MPIX + m0 + 4 * ty) = v0;
        *(float4*)(Cout + (size_t)n * MPIX + m0 + 64 + 4 * ty) = v1;
    }
}

// ---------------- fused out-layers + decode ----------------
#define STG16 (16 * 132)
__device__ __forceinline__ float sigmoidf_(float x) { return 1.f / (1.f + expf(-x)); }

__global__ void __launch_bounds__(256) outdec_k(
    const float* __restrict__ Acls, const float* __restrict__ Aobj, const float* __restrict__ Abox,
    const float* __restrict__ cw, const float* __restrict__ cb,
    const float* __restrict__ ow, const float* __restrict__ ob,
    const float* __restrict__ bw, const float* __restrict__ bbx)
{
    extern __shared__ __align__(16) float sm[];
    float* As_c = sm;
    float* As_b = sm + STG16;
    float* As_o = sm + 2 * STG16;
    float* Bsw  = sm + 3 * STG16;
    float* sbias = sm + 3 * STG16 + 1600;
    float* slog = sm + 3 * STG16 + 1712;

    const int m0 = blockIdx.x * 128;
    const int tid = threadIdx.x;
    const int tx = tid & 15, ty = tid >> 4;

    if (tid < 96) {
        float bv = 0.f;
        if (tid < 80) bv = cb[tid];
        else if (tid < 84) bv = bbx[tid - 80];
        else if (tid == 84) bv = ob[0];
        sbias[tid] = bv;
    }

    float acc[8][6];
    #pragma unroll
    for (int i = 0; i < 8; i++)
        #pragma unroll
        for (int j = 0; j < 6; j++) acc[i][j] = 0.f;

    #pragma unroll 1
    for (int p = 0; p < 16; p++) {
        __syncthreads();
        #pragma unroll
        for (int l = 0; l < 2; l++) {
            int idx = tid + l * 256;
            int k = idx >> 5, c4 = idx & 31;
            size_t off = (size_t)(p * 16 + k) * MPIX + m0 + c4 * 4;
            *(float4*)&As_c[k * 132 + c4 * 4] = *(const float4*)(Acls + off);
            *(float4*)&As_b[k * 132 + c4 * 4] = *(const float4*)(Abox + off);
            *(float4*)&As_o[k * 132 + c4 * 4] = *(const float4*)(Aobj + off);
        }
        #pragma unroll
        for (int l = 0; l < 6; l++) {
            int idx = tid + l * 256;
            int k = idx & 15, slot = idx >> 4;
            float v = 0.f;
            if (slot < 80)       v = cw[slot * 256 + p * 16 + k];
            else if (slot < 84)  v = bw[(slot - 80) * 256 + p * 16 + k];
            else if (slot == 84) v = ow[p * 16 + k];
            Bsw[k * 100 + slot] = v;
        }
        __syncthreads();

        const float* As_x = (tx < 4) ? As_b : (tx == 4 ? As_o : As_c);
        #pragma unroll
        for (int kk = 0; kk < 16; kk++) {
            float4 a0 = *(const float4*)&As_c[kk * 132 + ty * 8];
            float4 a1 = *(const float4*)&As_c[kk * 132 + ty * 8 + 4];
            float4 x0 = *(const float4*)&As_x[kk * 132 + ty * 8];
            float4 x1 = *(const float4*)&As_x[kk * 132 + ty * 8 + 4];
            float ac[8] = {a0.x, a0.y, a0.z, a0.w, a1.x, a1.y, a1.z, a1.w};
            float ax[8] = {x0.x, x0.y, x0.z, x0.w, x1.x, x1.y, x1.z, x1.w};
            float b[6];
            #pragma unroll
            for (int j = 0; j < 6; j++) b[j] = Bsw[kk * 100 + tx + 16 * j];
            #pragma unroll
            for (int i = 0; i < 8; i++) {
                #pragma unroll
                for (int j = 0; j < 5; j++)
                    acc[i][j] = fmaf(ac[i], b[j], acc[i][j]);
                acc[i][5] = fmaf(ax[i], b[5], acc[i][5]);
            }
        }
    }

    __syncthreads();
    #pragma unroll
    for (int i = 0; i < 8; i++)
        #pragma unroll
        for (int j = 0; j < 6; j++) {
            int col = tx + 16 * j;
            slog[(ty * 8 + i) * 97 + col] = acc[i][j] + sbias[col];
        }
    __syncthreads();

    if (tid < 128) {
        const float* lg = &slog[tid * 97];
        float objp = sigmoidf_(lg[84]);
        float best = -1.f; int bl = 0;
        #pragma unroll 4
        for (int c = 0; c < NCLS; c++) {
            float pr = sigmoidf_(lg[c]) * objp;
            if (pr > best) { best = pr; bl = c; }
        }
        int n = m0 + tid;
        g_score[n] = best;
        g_label[n] = bl;
        int hw = n & (HW - 1);
        int h = hw >> 7, w = hw & 127;
        float px = (w + 0.5f) * 8.f;
        float py = (h + 0.5f) * 8.f;
        float l = expf(lg[80]) * 8.f;
        float t = expf(lg[81]) * 8.f;
        float r = expf(lg[82]) * 8.f;
        float d = expf(lg[83]) * 8.f;
        g_boxes[(size_t)n * 4 + 0] = px - l;
        g_boxes[(size_t)n * 4 + 1] = py - t;
        g_boxes[(size_t)n * 4 + 2] = px + r;
        g_boxes[(size_t)n * 4 + 3] = py + d;
    }
}

// ---------------- exact top-1000: histogram select + compact + bitonic 4096 ----------------
__global__ void topk_k() {
    __shared__ int hist[256];
    __shared__ int s_b1, s_n1, s_thr, s_cnt;
    __shared__ unsigned long long skey[4096];
    int b = blockIdx.x;
    int tid = threadIdx.x;   // 1024

    if (tid < 256) hist[tid] = 0;
    __syncthreads();
    for (int i = tid; i < HW; i += 1024) {
        unsigned u = __float_as_uint(g_score[b * HW + i]);
        atomicAdd(&hist[u >> 24], 1);
    }
    __syncthreads();
    if (tid == 0) {
        int acc = 0; int bin = 255;
        for (; bin > 0; bin--) { if (acc + hist[bin] >= NMS_CAND) break; acc += hist[bin]; }
        s_b1 = bin; s_n1 = acc;
    }
    __syncthreads();
    int b1 = s_b1, n1 = s_n1;
    if (tid < 256) hist[tid] = 0;
    __syncthreads();
    for (int i = tid; i < HW; i += 1024) {
        unsigned u = __float_as_uint(g_score[b * HW + i]);
        if ((int)(u >> 24) == b1) atomicAdd(&hist[(u >> 16) & 255], 1);
    }
    __syncthreads();
    if (tid == 0) {
        int acc = n1; int bin = 255;
        for (; bin > 0; bin--) { if (acc + hist[bin] >= NMS_CAND) break; acc += hist[bin]; }
        s_thr = (b1 << 8) | bin;
        s_cnt = 0;
    }
    __syncthreads();
    unsigned thr = (unsigned)s_thr;
    for (int i = tid; i < HW; i += 1024) {
        unsigned u = __float_as_uint(g_score[b * HW + i]);
        if ((u >> 16) >= thr) {
            int pos = atomicAdd(&s_cnt, 1);
            if (pos < 4096)
                skey[pos] = ((unsigned long long)(~u) << 32) | (unsigned)i;
        }
    }
    __syncthreads();
    int cnt = s_cnt < 4096 ? s_cnt : 4096;
    for (int i = tid; i < 4096; i += 1024)
        if (i >= cnt) skey[i] = 0xFFFFFFFFFFFFFFFFull;
    __syncthreads();

    for (int k = 2; k <= 4096; k <<= 1) {
        for (int j = k >> 1; j > 0; j >>= 1) {
            #pragma unroll
            for (int l = 0; l < 4; l++) {
                int i = tid + l * 1024;
                int ixj = i ^ j;
                if (ixj > i) {
                    bool up = ((i & k) == 0);
                    unsigned long long a = skey[i], c = skey[ixj];
                    if (up ? (a > c) : (a < c)) { skey[i] = c; skey[ixj] = a; }
                }
            }
            __syncthreads();
        }
    }

    if (tid < NMS_CAND) {
        unsigned long long key = skey[tid];
        int idx = (int)(unsigned)key;
        float s = __uint_as_float(~(unsigned)(key >> 32));
        int g = b * HW + idx;
        int dst = b * NMS_CAND + tid;
        g_cand_sc[dst] = s;
        g_cand_lab[dst] = g_label[g];
        #pragma unroll
        for (int q = 0; q < 4; q++)
            g_cand_box[dst * 4 + q] = g_boxes[(size_t)g * 4 + q];
    }
}

// ---------------- NMS ----------------
__global__ void nms_mask_k() {
    int i = blockIdx.x;
    int b = blockIdx.y;
    int j = threadIdx.x;
    const float* bi = &g_cand_box[(b * NMS_CAND + i) * 4];
    float ix1 = bi[0], iy1 = bi[1], ix2 = bi[2], iy2 = bi[3];
    float ai = fmaxf(ix2 - ix1, 0.f) * fmaxf(iy2 - iy1, 0.f);
    bool pred = false;
    if (j < NMS_CAND && j > i) {
        const float* bj = &g_cand_box[(b * NMS_CAND + j) * 4];
        float aj = fmaxf(bj[2] - bj[0], 0.f) * fmaxf(bj[3] - bj[1], 0.f);
        float xx1 = fmaxf(ix1, bj[0]), yy1 = fmaxf(iy1, bj[1]);
        float xx2 = fminf(ix2, bj[2]), yy2 = fminf(iy2, bj[3]);
        float iw = fmaxf(xx2 - xx1, 0.f), ih = fmaxf(yy2 - yy1, 0.f);
        float inter = iw * ih;
        float iou = inter / (ai + aj - inter + 1e-6f);
        pred = iou > 0.65f;
    }
    unsigned m = __ballot_sync(0xffffffffu, pred);
    if ((j & 31) == 0)
        g_mask[((size_t)(b * NMS_CAND + i)) * 32 + (j >> 5)] = m;
}

__global__ void nms_reduce_k() {
    extern __shared__ unsigned smask[];
    int b = blockIdx.x;
    for (int t = threadIdx.x; t < NMS_CAND * 32; t += 1024)
        smask[t] = g_mask[(size_t)b * NMS_CAND * 32 + t];
    __syncthreads();
    if (threadIdx.x < 32) {
        int lane = threadIdx.x;
        unsigned removed = 0u;
        for (int i = 0; i < NMS_CAND; i++) {
            unsigned rw = __shfl_sync(0xffffffffu, removed, i >> 5);
            if (!((rw >> (i & 31)) & 1u))
                removed |= smask[i * 32 + lane];
        }
        g_keep[b * 32 + lane] = ~removed;
    }
}

// ---------------- final select ----------------
__global__ void select_k(float* __restrict__ out) {
    __shared__ int ps[1024];
    __shared__ int s_total;
    int b = blockIdx.x;
    int tid = threadIdx.x;
    int kept = 0;
    if (tid < NMS_CAND)
        kept = (g_keep[b * 32 + (tid >> 5)] >> (tid & 31)) & 1;
    ps[tid] = kept;
    __syncthreads();
    for (int off = 1; off < 1024; off <<= 1) {
        int v = (tid >= off) ? ps[tid - off] : 0;
        __syncthreads();
        ps[tid] += v;
        __syncthreads();
    }
    if (tid == 1023) s_total = ps[1023];
    __syncthreads();
    int total = s_total;
    if (tid < NMS_CAND) {
        int excl = ps[tid] - kept;
        int pos = kept ? excl : total + (tid - excl);
        if (pos < MAX_DET) {
            int src = b * NMS_CAND + tid;
            out[(b * MAX_DET + pos) * 4 + 0] = g_cand_box[src * 4 + 0];
            out[(b * MAX_DET + pos) * 4 + 1] = g_cand_box[src * 4 + 1];
            out[(b * MAX_DET + pos) * 4 + 2] = g_cand_box[src * 4 + 2];
            out[(b * MAX_DET + pos) * 4 + 3] = g_cand_box[src * 4 + 3];
            out[BB * MAX_DET * 4 + b * MAX_DET + pos] = kept ? g_cand_sc[src] : 0.f;
            out[BB * MAX_DET * 5 + b * MAX_DET + pos] = (float)g_cand_lab[src];
        }
    }
}

// ---------------- launch ----------------
extern "C" void kernel_launch(void* const* d_in, const int* in_sizes, int n_in,
                              void* d_out, int out_size) {
    (void)in_sizes; (void)n_in; (void)out_size;
    const float* feat = (const float*)d_in[0];
    const float* cls_w_in  = (const float*)d_in[1];
    const float* cls_b_in  = (const float*)d_in[2];
    const float* cls_w_hid = (const float*)d_in[3];
    const float* cls_b_hid = (const float*)d_in[4];
    const float* cls_w_out = (const float*)d_in[5];
    const float* cls_b_out = (const float*)d_in[6];
    const float* obj_w_in  = (const float*)d_in[7];
    const float* obj_b_in  = (const float*)d_in[8];
    const float* obj_w_hid = (const float*)d_in[9];
    const float* obj_b_hid = (const float*)d_in[10];
    const float* obj_w_out = (const float*)d_in[11];
    const float* obj_b_out = (const float*)d_in[12];
    const float* box_w_in  = (const float*)d_in[13];
    const float* box_b_in  = (const float*)d_in[14];
    const float* box_w_hid = (const float*)d_in[15];
    const float* box_b_hid = (const float*)d_in[16];
    const float* box_w_out = (const float*)d_in[17];
    const float* box_b_out = (const float*)d_in[18];
    float* out = (float*)d_out;

    float *X0, *bA, *bB, *WT;
    cudaGetSymbolAddress((void**)&X0, g_X0);
    cudaGetSymbolAddress((void**)&bA, g_bA);
    cudaGetSymbolAddress((void**)&bB, g_bB);
    cudaGetSymbolAddress((void**)&WT, g_WT);
    const size_t HS = (size_t)CC * MPIX;
    float* A[3] = {bA, bA + HS, bA + 2 * HS};
    float* Bt[3] = {bB, bB + HS, bB + 2 * HS};

    const int gemm_smem = 6 * STG * (int)sizeof(float);   // 101376 B (3 stages)
    const int outdec_smem = (3 * STG16 + 1712 + 128 * 97) * (int)sizeof(float);
    cudaFuncSetAttribute(gemm3_k, cudaFuncAttributeMaxDynamicSharedMemorySize, gemm_smem);
    cudaFuncSetAttribute(outdec_k, cudaFuncAttributeMaxDynamicSharedMemorySize, outdec_smem);
    cudaFuncSetAttribute(nms_reduce_k, cudaFuncAttributeMaxDynamicSharedMemorySize, 131072);

    // 0) prologue: pack feat + transpose all 15 weight matrices
    x0t_k<<<512, 256>>>(feat);
    wtrans_k<<<dim3(8, 8, 15), dim3(32, 8)>>>(cls_w_in, obj_w_in, box_w_in,
                                              cls_w_hid, obj_w_hid, box_w_hid);

    auto wt_in  = [&](int h) { return WT + (size_t)h * 65536; };
    auto wt_hid = [&](int h, int i) { return WT + (size_t)(3 + h * 4 + i) * 65536; };

    // 1) input layers
    dim3 gg(2, MPIX / 128, 3);
    gemm3_k<<<gg, 256, gemm_smem>>>(X0, X0, X0,
                                    wt_in(0), wt_in(1), wt_in(2),
                                    cls_b_in, obj_b_in, box_b_in,
                                    A[0], A[1], A[2], 0);
    // 2) hidden layers
    float* cur[3] = {A[0], A[1], A[2]};
    float* nxt[3] = {Bt[0], Bt[1], Bt[2]};
    for (int i = 0; i < 4; i++) {
        gemm3_k<<<gg, 256, gemm_smem>>>(cur[0], cur[1], cur[2],
                                        wt_hid(0, i), wt_hid(1, i), wt_hid(2, i),
                                        cls_b_hid + i * 256,
                                        obj_b_hid + i * 256,
                                        box_b_hid + i * 256,
                                        nxt[0], nxt[1], nxt[2], 1);
        for (int h = 0; h < 3; h++) { float* t = cur[h]; cur[h] = nxt[h]; nxt[h] = t; }
    }

    // 3) fused out-layers + decode
    outdec_k<<<MPIX / 128, 256, outdec_smem>>>(cur[0], cur[1], cur[2],
                                               cls_w_out, cls_b_out,
                                               obj_w_out, obj_b_out,
                                               box_w_out, box_b_out);

    // 4) exact per-batch top-1000
    topk_k<<<BB, 1024>>>();

    // 5) NMS
    nms_mask_k<<<dim3(NMS_CAND, BB), 1024>>>();
    nms_reduce_k<<<BB, 1024, NMS_CAND * 32 * (int)sizeof(unsigned)>>>();

    // 6) final top-100 select
    select_k<<<BB, 1024>>>(out);
}